// round 2
// baseline (speedup 1.0000x reference)
#include <cuda_runtime.h>
#include <cuda_bf16.h>
#include <math.h>

#define NNODES 3070
#define NFEAT 128
#define NOUT 64
#define HS 50
#define HSP 52           // padded row (16B aligned: 52*4=208)
#define NEDGES 49120
#define NB 128

// ---------------- device scratch (static, no allocations) ----------------
__device__ int   g_is64;
__device__ int   g_present[NNODES];
__device__ int   g_rank[NNODES];
__device__ float g_deg[NNODES];
__device__ float g_dinv[NNODES];
__device__ int   g_counts[NNODES];
__device__ int   g_csrptr[NNODES + 1];
__device__ int   g_cursor[NNODES];
__device__ int   g_esrc[NEDGES];
__device__ int   g_edst[NEDGES];
__device__ int   g_csrc[NEDGES];
__device__ float g_cw[NEDGES];
__device__ float g_M[NFEAT * HS];                    // M = W @ W_ih^T (128x50)
__device__ __align__(16) float g_cvec[HSP];          // c = b @ W_ih^T + b_ih
__device__ __align__(16) float g_u[(size_t)NB * NNODES * HSP + 16];
__device__ __align__(16) float g_pre[(size_t)NB * NNODES * HSP + 16];

// ---------------- setup: zero / detect dtype / fold weights ----------------
__global__ void k_setup(const void* eidx, const float* __restrict__ W,
                        const float* __restrict__ b,
                        const float* __restrict__ W_ih,
                        const float* __restrict__ b_ih) {
    int tid = blockIdx.x * blockDim.x + threadIdx.x;
    if (tid == 0) {
        // int64 edge_index => high 32-bit words all zero (ids < 3070)
        const int* p = (const int*)eidx;
        int is64 = 1;
        for (int i = 1; i < 512; i += 2) {
            if (p[i] != 0) { is64 = 0; break; }
        }
        g_is64 = is64;
        g_cvec[50] = 0.f; g_cvec[51] = 0.f;
    }
    if (tid < NNODES) {
        g_present[tid] = 0;
        g_deg[tid] = 1.0f;   // self-loop weight pre-added
        g_counts[tid] = 0;
    }
    int mi = tid - 4096;
    if (mi >= 0 && mi < NFEAT * HS) {
        int f = mi / HS, j = mi - f * HS;
        float s = 0.f;
        #pragma unroll 8
        for (int o = 0; o < NOUT; o++) s += W[f * NOUT + o] * W_ih[j * NOUT + o];
        g_M[mi] = s;
    }
    int ci = tid - 12000;
    if (ci >= 0 && ci < HS) {
        float s = b_ih[ci];
        #pragma unroll 8
        for (int o = 0; o < NOUT; o++) s += b[o] * W_ih[ci * NOUT + o];
        g_cvec[ci] = s;
    }
}

__device__ __forceinline__ int load_eid(const void* eidx, int i, int is64) {
    if (is64) return (int)((const long long*)eidx)[i];
    return ((const int*)eidx)[i];
}

// ---------------- mark present node ids ----------------
__global__ void k_mark(const void* eidx) {
    int i = blockIdx.x * 256 + threadIdx.x;
    if (i >= 2 * NEDGES) return;
    int v = load_eid(eidx, i, g_is64);
    g_present[v] = 1;
}

// ---------------- single-block exclusive scans ----------------
__global__ void k_scan(int mode) {
    __shared__ int sa[1024], sb[1024];
    int t = threadIdx.x;
    int base = t * 3;
    const int* in = mode ? g_counts : g_present;
    int v0 = (base     < NNODES) ? in[base]     : 0;
    int v1 = (base + 1 < NNODES) ? in[base + 1] : 0;
    int v2 = (base + 2 < NNODES) ? in[base + 2] : 0;
    int s = v0 + v1 + v2;
    sa[t] = s;
    __syncthreads();
    int* src = sa; int* dst = sb;
    for (int off = 1; off < 1024; off <<= 1) {
        int val = src[t];
        if (t >= off) val += src[t - off];
        dst[t] = val;
        __syncthreads();
        int* tmp = src; src = dst; dst = tmp;
    }
    int incl = src[t];
    int excl = incl - s;
    if (mode == 0) {
        if (base     < NNODES) g_rank[base]     = excl;
        if (base + 1 < NNODES) g_rank[base + 1] = excl + v0;
        if (base + 2 < NNODES) g_rank[base + 2] = excl + v0 + v1;
    } else {
        if (base < NNODES) {
            g_csrptr[base] = excl; g_cursor[base] = excl;
            g_dinv[base] = rsqrtf(g_deg[base]);
        }
        if (base + 1 < NNODES) {
            g_csrptr[base + 1] = excl + v0; g_cursor[base + 1] = excl + v0;
            g_dinv[base + 1] = rsqrtf(g_deg[base + 1]);
        }
        if (base + 2 < NNODES) {
            g_csrptr[base + 2] = excl + v0 + v1; g_cursor[base + 2] = excl + v0 + v1;
            g_dinv[base + 2] = rsqrtf(g_deg[base + 2]);
        }
        if (t == 1023) g_csrptr[NNODES] = incl;
    }
}

// ---------------- remap edges + degree/counts ----------------
__global__ void k_edges(const void* eidx, const float* __restrict__ ew) {
    int e = blockIdx.x * 256 + threadIdx.x;
    if (e >= NEDGES) return;
    int is64 = g_is64;
    int sid = load_eid(eidx, e, is64);
    int did = load_eid(eidx, NEDGES + e, is64);
    int s = g_rank[sid], d = g_rank[did];
    g_esrc[e] = s;
    g_edst[e] = d;
    atomicAdd(&g_deg[d], ew[e]);
    atomicAdd(&g_counts[d], 1);
}

// ---------------- fill CSR (by dst) with normalized weights ----------------
__global__ void k_fill(const float* __restrict__ ew) {
    int e = blockIdx.x * 256 + threadIdx.x;
    if (e >= NEDGES) return;
    int d = g_edst[e], s = g_esrc[e];
    int pos = atomicAdd(&g_cursor[d], 1);
    g_csrc[pos] = s;
    g_cw[pos] = g_dinv[s] * ew[e] * g_dinv[d];
}

// ---------------- GEMM: u = x @ M  (392960 x 128) @ (128 x 50), padded to 52 ----
// 3070 CTAs x 160 threads; thread tile: rows {rblk,+32,+64,+96}, cols {cblk+5j}.
// M transposed in smem so both operands are k-contiguous -> float4 LDS.
#define XSTR 132
#define GEMM_SMEM ((128 * XSTR + HS * XSTR) * 4)
__global__ void __launch_bounds__(160) k_gemm(const float* __restrict__ x) {
    extern __shared__ float sm[];
    float* xs = sm;                   // [128][132]
    float* ms = sm + 128 * XSTR;      // [50][132]: ms[c*XSTR + k] = M[k][c]
    int t = threadIdx.x;
    for (int i = t; i < NFEAT * HS; i += 160) {
        int f = i / HS, c = i - f * HS;
        ms[c * XSTR + f] = g_M[i];
    }
    size_t rowbase = (size_t)blockIdx.x * 128;
    const float4* x4 = (const float4*)(x + rowbase * NFEAT);
    for (int i = t; i < 128 * 32; i += 160) {
        int r = i >> 5, c = i & 31;
        float4 v = x4[i];
        *(float4*)&xs[r * XSTR + c * 4] = v;
    }
    __syncthreads();
    int rblk = t / 5, cblk = t - rblk * 5;
    float acc[4][10];
    #pragma unroll
    for (int i = 0; i < 4; i++)
        #pragma unroll
        for (int j = 0; j < 10; j++) acc[i][j] = 0.f;
    const float4* xp = (const float4*)&xs[rblk * XSTR];
    const int RS = 32 * XSTR / 4;   // 1056 float4 between row groups
    #pragma unroll 2
    for (int kk = 0; kk < 32; kk++) {
        float4 a0 = xp[kk];
        float4 a1 = xp[kk + RS];
        float4 a2 = xp[kk + 2 * RS];
        float4 a3 = xp[kk + 3 * RS];
        #pragma unroll
        for (int j = 0; j < 10; j++) {
            float4 m = ((const float4*)&ms[(cblk + 5 * j) * XSTR])[kk];
            acc[0][j] += a0.x * m.x + a0.y * m.y + a0.z * m.z + a0.w * m.w;
            acc[1][j] += a1.x * m.x + a1.y * m.y + a1.z * m.z + a1.w * m.w;
            acc[2][j] += a2.x * m.x + a2.y * m.y + a2.z * m.z + a2.w * m.w;
            acc[3][j] += a3.x * m.x + a3.y * m.y + a3.z * m.z + a3.w * m.w;
        }
    }
    __syncthreads();
    // stage as [128][52] (with zero padding) for vectorized coalesced store
    #pragma unroll
    for (int i = 0; i < 4; i++) {
        int r = rblk + 32 * i;
        #pragma unroll
        for (int j = 0; j < 10; j++) xs[r * HSP + cblk + 5 * j] = acc[i][j];
        if (cblk == 0) { xs[r * HSP + 50] = 0.f; xs[r * HSP + 51] = 0.f; }
    }
    __syncthreads();
    float4* uo = (float4*)(g_u + rowbase * HSP);
    const float4* st = (const float4*)xs;
    for (int i = t; i < 128 * HSP / 4; i += 160) uo[i] = st[i];
}

// ---------------- SpMM: pre[b,n,:] = sum_e w_e*u[b,src,:] + dinv^2*u[b,n,:] + c
// warp handles node n for 2 batches: lanes 0-12 batch 2bp, lanes 16-28 batch 2bp+1.
// One LDG.128 per edge per half-warp; 2-edge unroll for MLP.
__global__ void __launch_bounds__(256) k_spmm() {
    int gw = blockIdx.x * 8 + (threadIdx.x >> 5);
    int lane = threadIdx.x & 31;
    int bp = gw / NNODES;
    int n = gw - bp * NNODES;
    int b = bp * 2 + (lane >> 4);
    int li = lane & 15;
    bool act = li < 13;
    const float* ub = g_u + (size_t)b * (NNODES * HSP);
    int e0 = g_csrptr[n], e1 = g_csrptr[n + 1];
    float4 acc = make_float4(0.f, 0.f, 0.f, 0.f);
    int e = e0;
    for (; e + 1 < e1; e += 2) {
        int s0 = g_csrc[e];     float wv0 = g_cw[e];
        int s1 = g_csrc[e + 1]; float wv1 = g_cw[e + 1];
        float4 v0 = make_float4(0.f, 0.f, 0.f, 0.f);
        float4 v1 = make_float4(0.f, 0.f, 0.f, 0.f);
        if (act) v0 = *(const float4*)(ub + (size_t)s0 * HSP + li * 4);
        if (act) v1 = *(const float4*)(ub + (size_t)s1 * HSP + li * 4);
        acc.x += wv0 * v0.x; acc.y += wv0 * v0.y;
        acc.z += wv0 * v0.z; acc.w += wv0 * v0.w;
        acc.x += wv1 * v1.x; acc.y += wv1 * v1.y;
        acc.z += wv1 * v1.z; acc.w += wv1 * v1.w;
    }
    if (e < e1) {
        int s0 = g_csrc[e]; float wv0 = g_cw[e];
        float4 v0 = make_float4(0.f, 0.f, 0.f, 0.f);
        if (act) v0 = *(const float4*)(ub + (size_t)s0 * HSP + li * 4);
        acc.x += wv0 * v0.x; acc.y += wv0 * v0.y;
        acc.z += wv0 * v0.z; acc.w += wv0 * v0.w;
    }
    float dv = g_dinv[n];
    float ws = dv * dv;
    if (act) {
        float4 vs = *(const float4*)(ub + (size_t)n * HSP + li * 4);
        acc.x += ws * vs.x; acc.y += ws * vs.y;
        acc.z += ws * vs.z; acc.w += ws * vs.w;
        float4 cv = *(const float4*)(g_cvec + li * 4);
        acc.x += cv.x; acc.y += cv.y; acc.z += cv.z; acc.w += cv.w;
        float* pr = g_pre + ((size_t)b * NNODES + n) * HSP;
        *(float4*)(pr + li * 4) = acc;
    }
}

// ---------------- RNN: per-node independent 128-step recurrence ----------------
__global__ void __launch_bounds__(256) k_rnn(const float* __restrict__ Whh,
                                             const float* __restrict__ bhh,
                                             const float* __restrict__ h0,
                                             float* __restrict__ out) {
    int w = blockIdx.x * 8 + (threadIdx.x >> 5);
    int lane = threadIdx.x & 31;
    if (w >= NNODES) return;
    __shared__ __align__(16) float hsm[8][56];
    float* h = hsm[threadIdx.x >> 5];
    bool hi = lane < 18;
    int c1 = hi ? 32 + lane : 0;
    float w0[HSP], w1[HSP];
    #pragma unroll
    for (int k = 0; k < HS; k++) {
        w0[k] = Whh[lane * HS + k];
        w1[k] = Whh[c1 * HS + k];
    }
    w0[50] = w0[51] = 0.f;
    w1[50] = w1[51] = 0.f;
    float b0 = bhh[lane];
    float b1 = bhh[c1];
    h[lane] = h0[(size_t)w * HS + lane];
    if (hi) h[32 + lane] = h0[(size_t)w * HS + 32 + lane];
    if (lane == 0) { h[50] = 0.f; h[51] = 0.f; }
    __syncwarp();
    const float* prew = g_pre + (size_t)w * HSP;
    float* outw = out + (size_t)w * HS;
    const size_t pstr = (size_t)NNODES * HSP;
    const size_t ostr = (size_t)NNODES * HS;
    float pa0 = prew[lane];
    float pa1 = hi ? prew[32 + lane] : 0.f;
    for (int t = 0; t < NB; t++) {
        float a0 = pa0 + b0;
        float a1 = pa1 + b1;
        if (t + 1 < NB) {  // prefetch next step's pre row
            pa0 = prew[pstr + lane];
            pa1 = hi ? prew[pstr + 32 + lane] : 0.f;
        }
        prew += pstr;
        float s0 = 0.f, s1 = 0.f, s2 = 0.f, s3 = 0.f;
        #pragma unroll
        for (int k = 0; k < HSP; k += 4) {
            float4 hv = *(const float4*)&h[k];
            s0 += hv.x * w0[k]     + hv.y * w0[k + 1];
            s1 += hv.z * w0[k + 2] + hv.w * w0[k + 3];
            s2 += hv.x * w1[k]     + hv.y * w1[k + 1];
            s3 += hv.z * w1[k + 2] + hv.w * w1[k + 3];
        }
        float t0 = tanhf(a0 + s0 + s1);
        float t1 = tanhf(a1 + s2 + s3);
        __syncwarp();
        h[lane] = t0;
        if (hi) h[32 + lane] = t1;
        __syncwarp();
        outw[lane] = t0;
        if (hi) outw[32 + lane] = t1;
        outw += ostr;
    }
}

// ---------------- launch ----------------
extern "C" void kernel_launch(void* const* d_in, const int* in_sizes, int n_in,
                              void* d_out, int out_size) {
    const float* x    = (const float*)d_in[0];
    const void*  eidx = d_in[1];
    const float* ew   = (const float*)d_in[2];
    const float* W    = (const float*)d_in[3];
    const float* b    = (const float*)d_in[4];
    const float* W_ih = (const float*)d_in[5];
    const float* W_hh = (const float*)d_in[6];
    const float* b_ih = (const float*)d_in[7];
    const float* b_hh = (const float*)d_in[8];
    const float* h0   = (const float*)d_in[9];
    float* out = (float*)d_out;

    cudaFuncSetAttribute(k_gemm, cudaFuncAttributeMaxDynamicSharedMemorySize,
                         GEMM_SMEM);

    k_setup<<<64, 256>>>(eidx, W, b, W_ih, b_ih);             // 0
    k_mark<<<(2 * NEDGES + 255) / 256, 256>>>(eidx);          // 1
    k_scan<<<1, 1024>>>(0);                                   // 2
    k_edges<<<(NEDGES + 255) / 256, 256>>>(eidx, ew);         // 3
    k_scan<<<1, 1024>>>(1);                                   // 4
    k_gemm<<<NNODES, 160, GEMM_SMEM>>>(x);                    // 5 (ncu -s 5)
    k_fill<<<(NEDGES + 255) / 256, 256>>>(ew);                // 6
    k_spmm<<<(NB * NNODES / 2) / 8, 256>>>();                 // 7
    k_rnn<<<(NNODES + 7) / 8, 256>>>(W_hh, b_hh, h0, out);    // 8
}

// round 4
// speedup vs baseline: 1.0531x; 1.0531x over previous
#include <cuda_runtime.h>
#include <math.h>
#include <stdint.h>

#define NNODES 3070
#define NFEAT 128
#define NOUT 64
#define HS 50
#define HSP 52           // padded row, 208B
#define NEDGES 49120
#define NB 128
#define NROWS (NB * NNODES)

// ---------------- device scratch (static, no allocations) ----------------
__device__ int   g_present[NNODES];
__device__ int   g_rank[NNODES];
__device__ float g_dinv[NNODES];
__device__ int   g_csrptr[NNODES + 1];
__device__ int   g_esrc[NEDGES];
__device__ int   g_edst[NEDGES];
__device__ int   g_csrc[NEDGES];
__device__ float g_cw[NEDGES];
// B fragments in mma order: [s(16)][jp(4)][lane(32)][slot(4)] = 32KB
__device__ __align__(16) float g_Bfrag[16 * 4 * 32 * 4];
__device__ __align__(16) float g_cvec[HSP];
__device__ __align__(16) float g_u[(size_t)NROWS * HSP];
__device__ __align__(16) float g_pre[(size_t)NROWS * HSP];

__device__ __forceinline__ uint32_t to_tf32(float f) {
    uint32_t r;
    asm("cvt.rna.tf32.f32 %0, %1;" : "=r"(r) : "f"(f));
    return r;
}
__device__ __forceinline__ void mma_tf32(float* d, const uint32_t* a,
                                         uint32_t b0, uint32_t b1) {
    asm volatile(
        "mma.sync.aligned.m16n8k8.row.col.f32.tf32.tf32.f32 "
        "{%0,%1,%2,%3}, {%4,%5,%6,%7}, {%8,%9}, {%0,%1,%2,%3};"
        : "+f"(d[0]), "+f"(d[1]), "+f"(d[2]), "+f"(d[3])
        : "r"(a[0]), "r"(a[1]), "r"(a[2]), "r"(a[3]), "r"(b0), "r"(b1));
}

// ---------------- setup: B fragments (tf32, fold W@W_ih^T) + cvec ---------------
__global__ void k_setup(const float* __restrict__ W, const float* __restrict__ b,
                        const float* __restrict__ W_ih, const float* __restrict__ b_ih) {
    int i = blockIdx.x * 256 + threadIdx.x;
    if (i < 128 * 64) {
        int k = i >> 6, c = i & 63;
        float v = 0.f;
        if (c < HS) {
            float s = 0.f;
            #pragma unroll 8
            for (int o = 0; o < NOUT; o++) s += W[k * NOUT + o] * W_ih[c * NOUT + o];
            uint32_t t = to_tf32(s);
            v = __uint_as_float(t);
        }
        int sct = k >> 3, kr = k & 7, bidx = kr >> 2, klo = kr & 3;
        int j = c >> 3, nr = c & 7, jp = j >> 1, jodd = j & 1;
        int lane = nr * 4 + klo;
        g_Bfrag[(((sct * 4 + jp) * 32 + lane) << 2) + jodd * 2 + bidx] = v;
    }
    int ci = i - 128 * 64;
    if (ci >= 0 && ci < HS) {
        float s = b_ih[ci];
        #pragma unroll 8
        for (int o = 0; o < NOUT; o++) s += b[o] * W_ih[ci * NOUT + o];
        g_cvec[ci] = s;
    }
    if (ci == HS) { g_cvec[50] = 0.f; g_cvec[51] = 0.f; }
}

// ---------------- prep: all graph preprocessing in ONE single-CTA kernel --------
__global__ void __launch_bounds__(1024) k_prep(const void* eidx,
                                               const float* __restrict__ ew) {
    __shared__ int sa[1024], sb[1024];
    __shared__ int scnt[NNODES];
    __shared__ float sdeg[NNODES];
    __shared__ int sis64;
    int t = threadIdx.x;
    if (t == 0) {
        const int* p = (const int*)eidx;
        int is64 = 1;
        for (int i = 1; i < 512; i += 2)
            if (p[i] != 0) { is64 = 0; break; }
        sis64 = is64;
    }
    for (int i = t; i < NNODES; i += 1024) {
        g_present[i] = 0; scnt[i] = 0; sdeg[i] = 1.0f;
    }
    __syncthreads();
    int is64 = sis64;
    const long long* e64 = (const long long*)eidx;
    const int* e32 = (const int*)eidx;
    for (int i = t; i < 2 * NEDGES; i += 1024) {
        int v = is64 ? (int)e64[i] : e32[i];
        g_present[v] = 1;
    }
    __syncthreads();
    {   // scan present -> rank
        int base = t * 3;
        int v0 = (base < NNODES) ? g_present[base] : 0;
        int v1 = (base + 1 < NNODES) ? g_present[base + 1] : 0;
        int v2 = (base + 2 < NNODES) ? g_present[base + 2] : 0;
        int s = v0 + v1 + v2;
        sa[t] = s;
        __syncthreads();
        int* src = sa; int* dst = sb;
        for (int off = 1; off < 1024; off <<= 1) {
            int val = src[t];
            if (t >= off) val += src[t - off];
            dst[t] = val;
            __syncthreads();
            int* tmp = src; src = dst; dst = tmp;
        }
        int excl = src[t] - s;
        if (base < NNODES) g_rank[base] = excl;
        if (base + 1 < NNODES) g_rank[base + 1] = excl + v0;
        if (base + 2 < NNODES) g_rank[base + 2] = excl + v0 + v1;
    }
    __syncthreads();
    for (int e = t; e < NEDGES; e += 1024) {
        int sid = is64 ? (int)e64[e] : e32[e];
        int did = is64 ? (int)e64[NEDGES + e] : e32[NEDGES + e];
        int s = g_rank[sid], d = g_rank[did];
        g_esrc[e] = s; g_edst[e] = d;
        atomicAdd(&sdeg[d], ew[e]);
        atomicAdd(&scnt[d], 1);
    }
    __syncthreads();
    {   // scan counts -> csrptr; cursor back into scnt; dinv
        int base = t * 3;
        int v0 = (base < NNODES) ? scnt[base] : 0;
        int v1 = (base + 1 < NNODES) ? scnt[base + 1] : 0;
        int v2 = (base + 2 < NNODES) ? scnt[base + 2] : 0;
        int s = v0 + v1 + v2;
        __syncthreads();
        sa[t] = s;
        __syncthreads();
        int* src = sa; int* dst = sb;
        for (int off = 1; off < 1024; off <<= 1) {
            int val = src[t];
            if (t >= off) val += src[t - off];
            dst[t] = val;
            __syncthreads();
            int* tmp = src; src = dst; dst = tmp;
        }
        int incl = src[t];
        int excl = incl - s;
        if (base < NNODES) {
            g_csrptr[base] = excl; scnt[base] = excl;
            g_dinv[base] = rsqrtf(sdeg[base]);
        }
        if (base + 1 < NNODES) {
            g_csrptr[base + 1] = excl + v0; scnt[base + 1] = excl + v0;
            g_dinv[base + 1] = rsqrtf(sdeg[base + 1]);
        }
        if (base + 2 < NNODES) {
            g_csrptr[base + 2] = excl + v0 + v1; scnt[base + 2] = excl + v0 + v1;
            g_dinv[base + 2] = rsqrtf(sdeg[base + 2]);
        }
        if (t == 1023) g_csrptr[NNODES] = incl;
    }
    __syncthreads();
    for (int e = t; e < NEDGES; e += 1024) {
        int d = g_edst[e], s = g_esrc[e];
        int pos = atomicAdd(&scnt[d], 1);
        g_csrc[pos] = s;
        g_cw[pos] = g_dinv[s] * ew[e] * g_dinv[d];
    }
}

// ---------------- GEMM: u = x @ M via mma.sync tf32 m16n8k8 ---------------------
// CTA = 128 threads (4 warps); warp tile M=32 x N=56 (7 n-tiles), K=128.
// A from gmem->regs (double buffered), B fragments from smem (pre-shuffled).
__global__ void __launch_bounds__(128) k_gemm(const float* __restrict__ x) {
    __shared__ __align__(16) float4 Bs[16 * 4 * 32];
    int tid = threadIdx.x, wid = tid >> 5, lane = tid & 31;
    {
        const float4* s = (const float4*)g_Bfrag;
        #pragma unroll
        for (int i = 0; i < 16; i++) Bs[tid + 128 * i] = s[tid + 128 * i];
    }
    size_t rowbase = (size_t)blockIdx.x * 128;
    int grp = lane >> 2, qid = lane & 3;
    const float* px0 = x + (rowbase + wid * 32 + grp) * NFEAT + qid;
    const float* px1 = px0 + 16 * NFEAT;
    __syncthreads();

    float d[14][4];
    #pragma unroll
    for (int i = 0; i < 14; i++)
        #pragma unroll
        for (int j = 0; j < 4; j++) d[i][j] = 0.f;

    uint32_t aA[8], aB[8];
    #define LOADA(buf, s) do {                                     \
        int o = 8 * (s);                                           \
        (buf)[0] = to_tf32(px0[o]);                                \
        (buf)[1] = to_tf32(px0[o + 8 * NFEAT]);                    \
        (buf)[2] = to_tf32(px0[o + 4]);                            \
        (buf)[3] = to_tf32(px0[o + 8 * NFEAT + 4]);                \
        (buf)[4] = to_tf32(px1[o]);                                \
        (buf)[5] = to_tf32(px1[o + 8 * NFEAT]);                    \
        (buf)[6] = to_tf32(px1[o + 4]);                            \
        (buf)[7] = to_tf32(px1[o + 8 * NFEAT + 4]);                \
    } while (0)

    LOADA(aA, 0);
    #pragma unroll
    for (int s = 0; s < 16; s++) {
        uint32_t* cur = (s & 1) ? aB : aA;
        uint32_t* nxt = (s & 1) ? aA : aB;
        if (s < 15) LOADA(nxt, s + 1);
        float4 bv[4];
        #pragma unroll
        for (int jp = 0; jp < 4; jp++) bv[jp] = Bs[(s * 4 + jp) * 32 + lane];
        const uint32_t* bu = (const uint32_t*)bv;
        #pragma unroll
        for (int jt = 0; jt < 7; jt++) {
            uint32_t b0 = bu[jt * 2], b1 = bu[jt * 2 + 1];
            mma_tf32(d[jt], cur, b0, b1);
            mma_tf32(d[7 + jt], cur + 4, b0, b1);
        }
    }
    // epilogue: D fragment (row grp/(grp+8), cols 2*qid,2*qid+1 within n-tile)
    #pragma unroll
    for (int mt = 0; mt < 2; mt++) {
        size_t r0 = rowbase + wid * 32 + mt * 16 + grp;
        #pragma unroll
        for (int jt = 0; jt < 7; jt++) {
            int c0 = jt * 8 + 2 * qid;
            if (jt < 6 || qid == 0) {
                float* p = g_u + r0 * HSP + c0;
                *(float2*)p = make_float2(d[mt * 7 + jt][0], d[mt * 7 + jt][1]);
                *(float2*)(p + 8 * HSP) =
                    make_float2(d[mt * 7 + jt][2], d[mt * 7 + jt][3]);
            }
        }
    }
}

// ---------------- SpMM: warp per (b,n); lanes 0..24 hold float2 (cols 0..49) ----
__global__ void __launch_bounds__(256) k_spmm() {
    int gw = blockIdx.x * 8 + (threadIdx.x >> 5);
    int lane = threadIdx.x & 31;
    int b = gw / NNODES;
    int n = gw - b * NNODES;
    const float* ub = g_u + (size_t)b * (NNODES * HSP);
    int e0 = g_csrptr[n], e1 = g_csrptr[n + 1];
    bool act = lane < 25;
    int li = lane * 2;
    float ax = 0.f, ay = 0.f;
    int e = e0;
    for (; e + 3 < e1; e += 4) {
        int s0 = g_csrc[e];     float w0 = g_cw[e];
        int s1 = g_csrc[e + 1]; float w1 = g_cw[e + 1];
        int s2 = g_csrc[e + 2]; float w2 = g_cw[e + 2];
        int s3 = g_csrc[e + 3]; float w3 = g_cw[e + 3];
        float2 v0 = make_float2(0.f, 0.f), v1 = v0, v2 = v0, v3 = v0;
        if (act) {
            v0 = *(const float2*)(ub + (size_t)s0 * HSP + li);
            v1 = *(const float2*)(ub + (size_t)s1 * HSP + li);
            v2 = *(const float2*)(ub + (size_t)s2 * HSP + li);
            v3 = *(const float2*)(ub + (size_t)s3 * HSP + li);
        }
        ax += w0 * v0.x + w1 * v1.x + w2 * v2.x + w3 * v3.x;
        ay += w0 * v0.y + w1 * v1.y + w2 * v2.y + w3 * v3.y;
    }
    for (; e < e1; e++) {
        int s0 = g_csrc[e]; float w0 = g_cw[e];
        float2 v0 = make_float2(0.f, 0.f);
        if (act) v0 = *(const float2*)(ub + (size_t)s0 * HSP + li);
        ax += w0 * v0.x; ay += w0 * v0.y;
    }
    if (act) {
        float dv = g_dinv[n];
        float ws = dv * dv;
        float2 vs = *(const float2*)(ub + (size_t)n * HSP + li);
        float2 cv = *(const float2*)(g_cvec + li);
        ax += ws * vs.x + cv.x;
        ay += ws * vs.y + cv.y;
        *(float2*)(g_pre + (size_t)gw * HSP + li) = make_float2(ax, ay);
    }
}

// ---------------- RNN: warp per node, 128 sequential steps ----------------------
__global__ void __launch_bounds__(256) k_rnn(const float* __restrict__ Whh,
                                             const float* __restrict__ bhh,
                                             const float* __restrict__ h0,
                                             float* __restrict__ out) {
    int w = blockIdx.x * 8 + (threadIdx.x >> 5);
    int lane = threadIdx.x & 31;
    if (w >= NNODES) return;
    __shared__ __align__(16) float hsm[8][56];
    float* h = hsm[threadIdx.x >> 5];
    bool hi = lane < 18;
    int c1 = hi ? 32 + lane : 0;
    float w0[HSP], w1[HSP];
    #pragma unroll
    for (int k = 0; k < HS; k++) {
        w0[k] = Whh[lane * HS + k];
        w1[k] = Whh[c1 * HS + k];
    }
    w0[50] = w0[51] = 0.f;
    w1[50] = w1[51] = 0.f;
    float b0 = bhh[lane];
    float b1 = bhh[c1];
    h[lane] = h0[(size_t)w * HS + lane];
    if (hi) h[32 + lane] = h0[(size_t)w * HS + 32 + lane];
    if (lane == 0) { h[50] = 0.f; h[51] = 0.f; }
    __syncwarp();
    const float* prew = g_pre + (size_t)w * HSP;
    float* outw = out + (size_t)w * HS;
    const size_t pstr = (size_t)NNODES * HSP;
    const size_t ostr = (size_t)NNODES * HS;
    float pa0 = prew[lane];
    float pa1 = hi ? prew[32 + lane] : 0.f;
    for (int t = 0; t < NB; t++) {
        float a0 = pa0 + b0;
        float a1 = pa1 + b1;
        if (t + 1 < NB) {
            pa0 = prew[pstr + lane];
            pa1 = hi ? prew[pstr + 32 + lane] : 0.f;
        }
        prew += pstr;
        float s0 = 0.f, s1 = 0.f, s2 = 0.f, s3 = 0.f;
        #pragma unroll
        for (int k = 0; k < HSP; k += 4) {
            float4 hv = *(const float4*)&h[k];
            s0 += hv.x * w0[k]     + hv.y * w0[k + 1];
            s1 += hv.z * w0[k + 2] + hv.w * w0[k + 3];
            s2 += hv.x * w1[k]     + hv.y * w1[k + 1];
            s3 += hv.z * w1[k + 2] + hv.w * w1[k + 3];
        }
        float t0 = tanhf(a0 + s0 + s1);
        float t1 = tanhf(a1 + s2 + s3);
        __syncwarp();
        h[lane] = t0;
        if (hi) h[32 + lane] = t1;
        __syncwarp();
        outw[lane] = t0;
        if (hi) outw[32 + lane] = t1;
        outw += ostr;
    }
}

// ---------------- launch ----------------
extern "C" void kernel_launch(void* const* d_in, const int* in_sizes, int n_in,
                              void* d_out, int out_size) {
    const float* x    = (const float*)d_in[0];
    const void*  eidx = d_in[1];
    const float* ew   = (const float*)d_in[2];
    const float* W    = (const float*)d_in[3];
    const float* b    = (const float*)d_in[4];
    const float* W_ih = (const float*)d_in[5];
    const float* W_hh = (const float*)d_in[6];
    const float* b_ih = (const float*)d_in[7];
    const float* b_hh = (const float*)d_in[8];
    const float* h0   = (const float*)d_in[9];
    float* out = (float*)d_out;

    k_setup<<<33, 256>>>(W, b, W_ih, b_ih);                  // 0
    k_prep<<<1, 1024>>>(eidx, ew);                           // 1
    k_gemm<<<NNODES, 128>>>(x);                              // 2
    k_spmm<<<(NB * NNODES) / 8, 256>>>();                    // 3  <- profiled
    k_rnn<<<(NNODES + 7) / 8, 256>>>(W_hh, b_hh, h0, out);   // 4
}

// round 5
// speedup vs baseline: 1.2511x; 1.1880x over previous
#include <cuda_runtime.h>
#include <cuda_fp16.h>
#include <math.h>
#include <stdint.h>

#define NNODES 3070
#define NFEAT 128
#define NOUT 64
#define HS 50
#define HSP 52           // fp32 pre row: 52 floats = 13 x float4
#define USTR 64          // fp16 u row: 64 halves = 128B (one cache line)
#define NEDGES 49120
#define NB 128
#define NROWS (NB * NNODES)

// ---------------- device scratch (static, no allocations) ----------------
__device__ int   g_present[NNODES];
__device__ int   g_rank[NNODES];
__device__ float g_deg[NNODES];
__device__ float g_dinv[NNODES];
__device__ int   g_counts[NNODES];
__device__ int   g_csrptr[NNODES + 1];
__device__ int   g_cursor[NNODES];
__device__ int   g_esrc[NEDGES];
__device__ int   g_edst[NEDGES];
__device__ int   g_csrc[NEDGES];
__device__ float g_cw[NEDGES];
// B fragments in mma order: [s(16)][jp(4)][lane(32)][slot(4)] = 32KB
__device__ __align__(16) float g_Bfrag[16 * 4 * 32 * 4];
__device__ __align__(16) float g_cvec[HSP];
__device__ __align__(256) __half g_u[(size_t)NROWS * USTR];
__device__ __align__(16) float g_pre[(size_t)NROWS * HSP];

__device__ __forceinline__ uint32_t to_tf32(float f) {
    uint32_t r;
    asm("cvt.rna.tf32.f32 %0, %1;" : "=r"(r) : "f"(f));
    return r;
}
__device__ __forceinline__ void mma_tf32(float* d, const uint32_t* a,
                                         uint32_t b0, uint32_t b1) {
    asm volatile(
        "mma.sync.aligned.m16n8k8.row.col.f32.tf32.tf32.f32 "
        "{%0,%1,%2,%3}, {%4,%5,%6,%7}, {%8,%9}, {%0,%1,%2,%3};"
        : "+f"(d[0]), "+f"(d[1]), "+f"(d[2]), "+f"(d[3])
        : "r"(a[0]), "r"(a[1]), "r"(a[2]), "r"(a[3]), "r"(b0), "r"(b1));
}

// ---------------- setup: B fragments (tf32, fold W@W_ih^T) + cvec ---------------
__global__ void k_setup(const float* __restrict__ W, const float* __restrict__ b,
                        const float* __restrict__ W_ih, const float* __restrict__ b_ih) {
    int i = blockIdx.x * 256 + threadIdx.x;
    if (i < 128 * 64) {
        int k = i >> 6, c = i & 63;
        float v = 0.f;
        if (c < HS) {
            float s = 0.f;
            #pragma unroll 8
            for (int o = 0; o < NOUT; o++) s += W[k * NOUT + o] * W_ih[c * NOUT + o];
            v = __uint_as_float(to_tf32(s));
        }
        int sct = k >> 3, kr = k & 7, bidx = kr >> 2, klo = kr & 3;
        int j = c >> 3, nr = c & 7, jp = j >> 1, jodd = j & 1;
        int lane = nr * 4 + klo;
        g_Bfrag[(((sct * 4 + jp) * 32 + lane) << 2) + jodd * 2 + bidx] = v;
    }
    int ci = i - 128 * 64;
    if (ci >= 0 && ci < HS) {
        float s = b_ih[ci];
        #pragma unroll 8
        for (int o = 0; o < NOUT; o++) s += b[o] * W_ih[ci * NOUT + o];
        g_cvec[ci] = s;
    }
    if (ci == HS) { g_cvec[50] = 0.f; g_cvec[51] = 0.f; }
}

__device__ __forceinline__ int load_eid(const void* eidx, int i, int is64) {
    if (is64) return (int)((const long long*)eidx)[i];
    return ((const int*)eidx)[i];
}
__device__ int g_is64;

// ---------------- mark present node ids (+ dtype detect + init) -----------------
__global__ void k_mark(const void* eidx) {
    int i = blockIdx.x * 256 + threadIdx.x;
    if (i == 0) {
        const int* p = (const int*)eidx;
        int is64 = 1;
        for (int j = 1; j < 512; j += 2)
            if (p[j] != 0) { is64 = 0; break; }
        g_is64 = is64;
    }
    if (i < NNODES) {
        g_present[i] = 0; g_deg[i] = 1.0f; g_counts[i] = 0;
    }
}
__global__ void k_mark2(const void* eidx) {
    int i = blockIdx.x * 256 + threadIdx.x;
    if (i >= 2 * NEDGES) return;
    g_present[load_eid(eidx, i, g_is64)] = 1;
}

// ---------------- single-block exclusive scans ----------------
__global__ void k_scan(int mode) {
    __shared__ int sa[1024], sb[1024];
    int t = threadIdx.x;
    int base = t * 3;
    const int* in = mode ? g_counts : g_present;
    int v0 = (base     < NNODES) ? in[base]     : 0;
    int v1 = (base + 1 < NNODES) ? in[base + 1] : 0;
    int v2 = (base + 2 < NNODES) ? in[base + 2] : 0;
    int s = v0 + v1 + v2;
    sa[t] = s;
    __syncthreads();
    int* src = sa; int* dst = sb;
    for (int off = 1; off < 1024; off <<= 1) {
        int val = src[t];
        if (t >= off) val += src[t - off];
        dst[t] = val;
        __syncthreads();
        int* tmp = src; src = dst; dst = tmp;
    }
    int incl = src[t];
    int excl = incl - s;
    if (mode == 0) {
        if (base     < NNODES) g_rank[base]     = excl;
        if (base + 1 < NNODES) g_rank[base + 1] = excl + v0;
        if (base + 2 < NNODES) g_rank[base + 2] = excl + v0 + v1;
    } else {
        if (base < NNODES) {
            g_csrptr[base] = excl; g_cursor[base] = excl;
            g_dinv[base] = rsqrtf(g_deg[base]);
        }
        if (base + 1 < NNODES) {
            g_csrptr[base + 1] = excl + v0; g_cursor[base + 1] = excl + v0;
            g_dinv[base + 1] = rsqrtf(g_deg[base + 1]);
        }
        if (base + 2 < NNODES) {
            g_csrptr[base + 2] = excl + v0 + v1; g_cursor[base + 2] = excl + v0 + v1;
            g_dinv[base + 2] = rsqrtf(g_deg[base + 2]);
        }
        if (t == 1023) g_csrptr[NNODES] = incl;
    }
}

// ---------------- remap edges + degree/counts ----------------
__global__ void k_edges(const void* eidx, const float* __restrict__ ew) {
    int e = blockIdx.x * 256 + threadIdx.x;
    if (e >= NEDGES) return;
    int is64 = g_is64;
    int sid = load_eid(eidx, e, is64);
    int did = load_eid(eidx, NEDGES + e, is64);
    int s = g_rank[sid], d = g_rank[did];
    g_esrc[e] = s;
    g_edst[e] = d;
    atomicAdd(&g_deg[d], ew[e]);
    atomicAdd(&g_counts[d], 1);
}

// ---------------- fill CSR (by dst) with normalized weights ----------------
__global__ void k_fill(const float* __restrict__ ew) {
    int e = blockIdx.x * 256 + threadIdx.x;
    if (e >= NEDGES) return;
    int d = g_edst[e], s = g_esrc[e];
    int pos = atomicAdd(&g_cursor[d], 1);
    g_csrc[pos] = s;
    g_cw[pos] = g_dinv[s] * ew[e] * g_dinv[d];
}

// ---------------- GEMM: u = x @ M via mma.sync tf32 m16n8k8, fp16 out -----------
__global__ void __launch_bounds__(128) k_gemm(const float* __restrict__ x) {
    __shared__ __align__(16) float4 Bs[16 * 4 * 32];
    int tid = threadIdx.x, wid = tid >> 5, lane = tid & 31;
    {
        const float4* s = (const float4*)g_Bfrag;
        #pragma unroll
        for (int i = 0; i < 16; i++) Bs[tid + 128 * i] = s[tid + 128 * i];
    }
    size_t rowbase = (size_t)blockIdx.x * 128;
    int grp = lane >> 2, qid = lane & 3;
    const float* px0 = x + (rowbase + wid * 32 + grp) * NFEAT + qid;
    const float* px1 = px0 + 16 * NFEAT;
    __syncthreads();

    float d[14][4];
    #pragma unroll
    for (int i = 0; i < 14; i++)
        #pragma unroll
        for (int j = 0; j < 4; j++) d[i][j] = 0.f;

    uint32_t aA[8], aB[8];
    #define LOADA(buf, s) do {                                     \
        int o = 8 * (s);                                           \
        (buf)[0] = to_tf32(px0[o]);                                \
        (buf)[1] = to_tf32(px0[o + 8 * NFEAT]);                    \
        (buf)[2] = to_tf32(px0[o + 4]);                            \
        (buf)[3] = to_tf32(px0[o + 8 * NFEAT + 4]);                \
        (buf)[4] = to_tf32(px1[o]);                                \
        (buf)[5] = to_tf32(px1[o + 8 * NFEAT]);                    \
        (buf)[6] = to_tf32(px1[o + 4]);                            \
        (buf)[7] = to_tf32(px1[o + 8 * NFEAT + 4]);                \
    } while (0)

    LOADA(aA, 0);
    #pragma unroll
    for (int s = 0; s < 16; s++) {
        uint32_t* cur = (s & 1) ? aB : aA;
        uint32_t* nxt = (s & 1) ? aA : aB;
        if (s < 15) LOADA(nxt, s + 1);
        float4 bv[4];
        #pragma unroll
        for (int jp = 0; jp < 4; jp++) bv[jp] = Bs[(s * 4 + jp) * 32 + lane];
        const uint32_t* bu = (const uint32_t*)bv;
        #pragma unroll
        for (int jt = 0; jt < 7; jt++) {
            uint32_t b0 = bu[jt * 2], b1 = bu[jt * 2 + 1];
            mma_tf32(d[jt], cur, b0, b1);
            mma_tf32(d[7 + jt], cur + 4, b0, b1);
        }
    }
    // epilogue: half2 stores; zero-fill pad cols 50..63
    __half2 z2 = __float2half2_rn(0.f);
    #pragma unroll
    for (int mt = 0; mt < 2; mt++) {
        size_t r0 = rowbase + wid * 32 + mt * 16 + grp;
        __half* p0 = g_u + r0 * USTR;
        #pragma unroll
        for (int jt = 0; jt < 7; jt++) {
            int c0 = jt * 8 + 2 * qid;
            __half2 lo, hi;
            if (jt < 6 || qid == 0) {
                lo = __floats2half2_rn(d[mt * 7 + jt][0], d[mt * 7 + jt][1]);
                hi = __floats2half2_rn(d[mt * 7 + jt][2], d[mt * 7 + jt][3]);
            } else { lo = z2; hi = z2; }
            *(__half2*)(p0 + c0) = lo;
            *(__half2*)(p0 + 8 * USTR + c0) = hi;
        }
        int c0 = 56 + 2 * qid;
        *(__half2*)(p0 + c0) = z2;
        *(__half2*)(p0 + 8 * USTR + c0) = z2;
    }
}

// ---------------- SpMM: warp per (b,n); 2 half-warps x 2 edges, fp16 payload ----
__global__ void __launch_bounds__(256) k_spmm() {
    int gw = blockIdx.x * 8 + (threadIdx.x >> 5);
    int lane = threadIdx.x & 31;
    int b = gw / NNODES;
    int n = gw - b * NNODES;
    const __half* ub = g_u + (size_t)b * (NNODES * USTR);
    int e0 = g_csrptr[n], e1 = g_csrptr[n + 1];
    int grp = lane >> 4, li = lane & 15;
    float ax = 0.f, ay = 0.f, az = 0.f, aw = 0.f;
    int e = e0 + grp;
    for (; e + 2 < e1; e += 4) {
        int s0 = g_csrc[e];     float w0 = g_cw[e];
        int s1 = g_csrc[e + 2]; float w1 = g_cw[e + 2];
        uint2 v0 = *(const uint2*)(ub + (size_t)s0 * USTR + li * 4);
        uint2 v1 = *(const uint2*)(ub + (size_t)s1 * USTR + li * 4);
        float2 p0 = __half22float2(*(__half2*)&v0.x);
        float2 q0 = __half22float2(*(__half2*)&v0.y);
        float2 p1 = __half22float2(*(__half2*)&v1.x);
        float2 q1 = __half22float2(*(__half2*)&v1.y);
        ax += w0 * p0.x + w1 * p1.x;
        ay += w0 * p0.y + w1 * p1.y;
        az += w0 * q0.x + w1 * q1.x;
        aw += w0 * q0.y + w1 * q1.y;
    }
    if (e < e1) {
        int s0 = g_csrc[e]; float w0 = g_cw[e];
        uint2 v0 = *(const uint2*)(ub + (size_t)s0 * USTR + li * 4);
        float2 p0 = __half22float2(*(__half2*)&v0.x);
        float2 q0 = __half22float2(*(__half2*)&v0.y);
        ax += w0 * p0.x; ay += w0 * p0.y;
        az += w0 * q0.x; aw += w0 * q0.y;
    }
    ax += __shfl_xor_sync(0xffffffffu, ax, 16);
    ay += __shfl_xor_sync(0xffffffffu, ay, 16);
    az += __shfl_xor_sync(0xffffffffu, az, 16);
    aw += __shfl_xor_sync(0xffffffffu, aw, 16);
    if (grp == 0 && li < 13) {
        float dv = g_dinv[n];
        float ws = dv * dv;
        uint2 vs = *(const uint2*)(ub + (size_t)n * USTR + li * 4);
        float2 ps = __half22float2(*(__half2*)&vs.x);
        float2 qs = __half22float2(*(__half2*)&vs.y);
        float4 cv = *(const float4*)(g_cvec + li * 4);
        *(float4*)(g_pre + (size_t)gw * HSP + li * 4) = make_float4(
            ax + ws * ps.x + cv.x, ay + ws * ps.y + cv.y,
            az + ws * qs.x + cv.z, aw + ws * qs.y + cv.w);
    }
}

// ---------------- RNN: warp per node, 128 sequential steps ----------------------
__global__ void __launch_bounds__(256) k_rnn(const float* __restrict__ Whh,
                                             const float* __restrict__ bhh,
                                             const float* __restrict__ h0,
                                             float* __restrict__ out) {
    int w = blockIdx.x * 8 + (threadIdx.x >> 5);
    int lane = threadIdx.x & 31;
    if (w >= NNODES) return;
    __shared__ __align__(16) float hsm[8][56];
    float* h = hsm[threadIdx.x >> 5];
    bool hi = lane < 18;
    int c1 = hi ? 32 + lane : 0;
    float w0[HSP], w1[HSP];
    #pragma unroll
    for (int k = 0; k < HS; k++) {
        w0[k] = Whh[lane * HS + k];
        w1[k] = Whh[c1 * HS + k];
    }
    w0[50] = w0[51] = 0.f;
    w1[50] = w1[51] = 0.f;
    float b0 = bhh[lane];
    float b1 = bhh[c1];
    h[lane] = h0[(size_t)w * HS + lane];
    if (hi) h[32 + lane] = h0[(size_t)w * HS + 32 + lane];
    if (lane == 0) { h[50] = 0.f; h[51] = 0.f; }
    __syncwarp();
    const float* prew = g_pre + (size_t)w * HSP;
    float* outw = out + (size_t)w * HS;
    const size_t pstr = (size_t)NNODES * HSP;
    const size_t ostr = (size_t)NNODES * HS;
    float pa0 = prew[lane];
    float pa1 = hi ? prew[32 + lane] : 0.f;
    for (int t = 0; t < NB; t++) {
        float a0 = pa0 + b0;
        float a1 = pa1 + b1;
        if (t + 1 < NB) {
            pa0 = prew[pstr + lane];
            pa1 = hi ? prew[pstr + 32 + lane] : 0.f;
        }
        prew += pstr;
        float s0 = 0.f, s1 = 0.f, s2 = 0.f, s3 = 0.f;
        #pragma unroll
        for (int k = 0; k < HSP; k += 4) {
            float4 hv = *(const float4*)&h[k];
            s0 += hv.x * w0[k]     + hv.y * w0[k + 1];
            s1 += hv.z * w0[k + 2] + hv.w * w0[k + 3];
            s2 += hv.x * w1[k]     + hv.y * w1[k + 1];
            s3 += hv.z * w1[k + 2] + hv.w * w1[k + 3];
        }
        float t0 = tanhf(a0 + s0 + s1);
        float t1 = tanhf(a1 + s2 + s3);
        __syncwarp();
        h[lane] = t0;
        if (hi) h[32 + lane] = t1;
        __syncwarp();
        outw[lane] = t0;
        if (hi) outw[32 + lane] = t1;
        outw += ostr;
    }
}

// ---------------- launch ----------------
extern "C" void kernel_launch(void* const* d_in, const int* in_sizes, int n_in,
                              void* d_out, int out_size) {
    const float* x    = (const float*)d_in[0];
    const void*  eidx = d_in[1];
    const float* ew   = (const float*)d_in[2];
    const float* W    = (const float*)d_in[3];
    const float* b    = (const float*)d_in[4];
    const float* W_ih = (const float*)d_in[5];
    const float* W_hh = (const float*)d_in[6];
    const float* b_ih = (const float*)d_in[7];
    const float* b_hh = (const float*)d_in[8];
    const float* h0   = (const float*)d_in[9];
    float* out = (float*)d_out;

    k_setup<<<33, 256>>>(W, b, W_ih, b_ih);                  // 0
    k_mark<<<(NNODES + 255) / 256, 256>>>(eidx);             // 1
    k_mark2<<<(2 * NEDGES + 255) / 256, 256>>>(eidx);        // 2
    k_gemm<<<NNODES, 128>>>(x);                              // 3  <- profiled
    k_scan<<<1, 1024>>>(0);                                  // 4
    k_edges<<<(NEDGES + 255) / 256, 256>>>(eidx, ew);        // 5
    k_scan<<<1, 1024>>>(1);                                  // 6
    k_fill<<<(NEDGES + 255) / 256, 256>>>(ew);               // 7
    k_spmm<<<(NB * NNODES) / 8, 256>>>();                    // 8
    k_rnn<<<(NNODES + 7) / 8, 256>>>(W_hh, b_hh, h0, out);   // 9
}

// round 6
// speedup vs baseline: 1.3479x; 1.0774x over previous
#include <cuda_runtime.h>
#include <cuda_fp16.h>
#include <math.h>
#include <stdint.h>

#define NNODES 3070
#define NFEAT 128
#define NOUT 64
#define HS 50
#define HSP 52           // fp32 pre row: 52 floats = 13 x float4
#define USTR 64          // fp16 u row: 64 halves = 128B (one cache line)
#define NEDGES 49120
#define NB 128
#define NROWS (NB * NNODES)

// ---------------- device scratch (static, no allocations) ----------------
__device__ int   g_present[NNODES];
__device__ int   g_rank[NNODES];
__device__ float g_deg[NNODES];
__device__ float g_dinv[NNODES];
__device__ int   g_counts[NNODES];
__device__ int   g_csrptr[NNODES + 1];
__device__ int   g_cursor[NNODES];
__device__ int   g_esrc[NEDGES];
__device__ int   g_edst[NEDGES];
__device__ int   g_csrc[NEDGES];
__device__ float g_cw[NEDGES];
// B fragments in mma order: [s(16)][jp(4)][lane(32)][slot(4)] = 32KB
__device__ __align__(16) float g_Bfrag[16 * 4 * 32 * 4];
__device__ __align__(16) float g_cvec[HSP];
__device__ __align__(256) __half g_u[(size_t)NROWS * USTR];
__device__ __align__(16) float g_pre[(size_t)NROWS * HSP];

__device__ __forceinline__ uint32_t to_tf32(float f) {
    uint32_t r;
    asm("cvt.rna.tf32.f32 %0, %1;" : "=r"(r) : "f"(f));
    return r;
}
__device__ __forceinline__ void mma_tf32(float* d, const uint32_t* a,
                                         uint32_t b0, uint32_t b1) {
    asm volatile(
        "mma.sync.aligned.m16n8k8.row.col.f32.tf32.tf32.f32 "
        "{%0,%1,%2,%3}, {%4,%5,%6,%7}, {%8,%9}, {%0,%1,%2,%3};"
        : "+f"(d[0]), "+f"(d[1]), "+f"(d[2]), "+f"(d[3])
        : "r"(a[0]), "r"(a[1]), "r"(a[2]), "r"(a[3]), "r"(b0), "r"(b1));
}

// ---------------- setup: B fragments (tf32, K-permuted) + cvec ------------------
// K permutation: within each 16-col group t, slot q of step 2t holds cols
// {4q, 4q+1} (b0,b1), slot q of step 2t+1 holds {4q+2, 4q+3}. Inverse:
// k = 16t + 4q + r: step = 2t + (r>>1), bidx = r&1, klo = q.
__global__ void k_setup(const float* __restrict__ W, const float* __restrict__ b,
                        const float* __restrict__ W_ih, const float* __restrict__ b_ih) {
    int i = blockIdx.x * 256 + threadIdx.x;
    if (i < 128 * 64) {
        int k = i >> 6, c = i & 63;
        float v = 0.f;
        if (c < HS) {
            float s = 0.f;
            #pragma unroll 8
            for (int o = 0; o < NOUT; o++) s += W[k * NOUT + o] * W_ih[c * NOUT + o];
            v = __uint_as_float(to_tf32(s));
        }
        int t16 = k >> 4, j = k & 15, q = j >> 2, r = j & 3;
        int sct = 2 * t16 + (r >> 1);
        int bidx = r & 1;
        int klo = q;
        int jcol = c >> 3, nr = c & 7, jp = jcol >> 1, jodd = jcol & 1;
        int lane = nr * 4 + klo;
        g_Bfrag[(((sct * 4 + jp) * 32 + lane) << 2) + jodd * 2 + bidx] = v;
    }
    int ci = i - 128 * 64;
    if (ci >= 0 && ci < HS) {
        float s = b_ih[ci];
        #pragma unroll 8
        for (int o = 0; o < NOUT; o++) s += b[o] * W_ih[ci * NOUT + o];
        g_cvec[ci] = s;
    }
    if (ci == HS) { g_cvec[50] = 0.f; g_cvec[51] = 0.f; }
}

__device__ __forceinline__ int load_eid(const void* eidx, int i, int is64) {
    if (is64) return (int)((const long long*)eidx)[i];
    return ((const int*)eidx)[i];
}
__device__ int g_is64;

// ---------------- mark present node ids (+ dtype detect + init) -----------------
__global__ void k_mark(const void* eidx) {
    int i = blockIdx.x * 256 + threadIdx.x;
    if (i == 0) {
        const int* p = (const int*)eidx;
        int is64 = 1;
        for (int j = 1; j < 512; j += 2)
            if (p[j] != 0) { is64 = 0; break; }
        g_is64 = is64;
    }
    if (i < NNODES) {
        g_present[i] = 0; g_deg[i] = 1.0f; g_counts[i] = 0;
    }
}
__global__ void k_mark2(const void* eidx) {
    int i = blockIdx.x * 256 + threadIdx.x;
    if (i >= 2 * NEDGES) return;
    g_present[load_eid(eidx, i, g_is64)] = 1;
}

// ---------------- single-block exclusive scans ----------------
__global__ void k_scan(int mode) {
    __shared__ int sa[1024], sb[1024];
    int t = threadIdx.x;
    int base = t * 3;
    const int* in = mode ? g_counts : g_present;
    int v0 = (base     < NNODES) ? in[base]     : 0;
    int v1 = (base + 1 < NNODES) ? in[base + 1] : 0;
    int v2 = (base + 2 < NNODES) ? in[base + 2] : 0;
    int s = v0 + v1 + v2;
    sa[t] = s;
    __syncthreads();
    int* src = sa; int* dst = sb;
    for (int off = 1; off < 1024; off <<= 1) {
        int val = src[t];
        if (t >= off) val += src[t - off];
        dst[t] = val;
        __syncthreads();
        int* tmp = src; src = dst; dst = tmp;
    }
    int incl = src[t];
    int excl = incl - s;
    if (mode == 0) {
        if (base     < NNODES) g_rank[base]     = excl;
        if (base + 1 < NNODES) g_rank[base + 1] = excl + v0;
        if (base + 2 < NNODES) g_rank[base + 2] = excl + v0 + v1;
    } else {
        if (base < NNODES) {
            g_csrptr[base] = excl; g_cursor[base] = excl;
            g_dinv[base] = rsqrtf(g_deg[base]);
        }
        if (base + 1 < NNODES) {
            g_csrptr[base + 1] = excl + v0; g_cursor[base + 1] = excl + v0;
            g_dinv[base + 1] = rsqrtf(g_deg[base + 1]);
        }
        if (base + 2 < NNODES) {
            g_csrptr[base + 2] = excl + v0 + v1; g_cursor[base + 2] = excl + v0 + v1;
            g_dinv[base + 2] = rsqrtf(g_deg[base + 2]);
        }
        if (t == 1023) g_csrptr[NNODES] = incl;
    }
}

// ---------------- remap edges + degree/counts ----------------
__global__ void k_edges(const void* eidx, const float* __restrict__ ew) {
    int e = blockIdx.x * 256 + threadIdx.x;
    if (e >= NEDGES) return;
    int is64 = g_is64;
    int sid = load_eid(eidx, e, is64);
    int did = load_eid(eidx, NEDGES + e, is64);
    int s = g_rank[sid], d = g_rank[did];
    g_esrc[e] = s;
    g_edst[e] = d;
    atomicAdd(&g_deg[d], ew[e]);
    atomicAdd(&g_counts[d], 1);
}

// ---------------- fill CSR (by dst) with normalized weights ----------------
__global__ void k_fill(const float* __restrict__ ew) {
    int e = blockIdx.x * 256 + threadIdx.x;
    if (e >= NEDGES) return;
    int d = g_edst[e], s = g_esrc[e];
    int pos = atomicAdd(&g_cursor[d], 1);
    g_csrc[pos] = s;
    g_cw[pos] = g_dinv[s] * ew[e] * g_dinv[d];
}

// ---------------- GEMM: u = x @ M via mma.sync tf32 m16n8k8, fp16 out -----------
// A loads: K-permuted so each thread fetches float4 covering a0/a2 of 2 k-steps.
__global__ void __launch_bounds__(128) k_gemm(const float* __restrict__ x) {
    __shared__ __align__(16) float4 Bs[16 * 4 * 32];
    int tid = threadIdx.x, wid = tid >> 5, lane = tid & 31;
    {
        const float4* s = (const float4*)g_Bfrag;
        #pragma unroll
        for (int i = 0; i < 16; i++) Bs[tid + 128 * i] = s[tid + 128 * i];
    }
    size_t rowbase = (size_t)blockIdx.x * 128;
    int grp = lane >> 2, qid = lane & 3;
    const float* px = x + (rowbase + wid * 32 + grp) * NFEAT + 4 * qid;
    __syncthreads();

    float d[14][4];
    #pragma unroll
    for (int i = 0; i < 14; i++)
        #pragma unroll
        for (int j = 0; j < 4; j++) d[i][j] = 0.f;

    #pragma unroll
    for (int t = 0; t < 8; t++) {
        // rows grp, grp+8 (m-tile 0), grp+16, grp+24 (m-tile 1)
        float4 v0 = *(const float4*)(px + 16 * t);
        float4 v1 = *(const float4*)(px + 8 * NFEAT + 16 * t);
        float4 v2 = *(const float4*)(px + 16 * NFEAT + 16 * t);
        float4 v3 = *(const float4*)(px + 24 * NFEAT + 16 * t);
        #pragma unroll
        for (int ss = 0; ss < 2; ss++) {
            int s = 2 * t + ss;
            uint32_t am0[4], am1[4];
            if (ss == 0) {
                am0[0] = to_tf32(v0.x); am0[1] = to_tf32(v1.x);
                am0[2] = to_tf32(v0.y); am0[3] = to_tf32(v1.y);
                am1[0] = to_tf32(v2.x); am1[1] = to_tf32(v3.x);
                am1[2] = to_tf32(v2.y); am1[3] = to_tf32(v3.y);
            } else {
                am0[0] = to_tf32(v0.z); am0[1] = to_tf32(v1.z);
                am0[2] = to_tf32(v0.w); am0[3] = to_tf32(v1.w);
                am1[0] = to_tf32(v2.z); am1[1] = to_tf32(v3.z);
                am1[2] = to_tf32(v2.w); am1[3] = to_tf32(v3.w);
            }
            float4 bv[4];
            #pragma unroll
            for (int jp = 0; jp < 4; jp++) bv[jp] = Bs[(s * 4 + jp) * 32 + lane];
            const uint32_t* bu = (const uint32_t*)bv;
            #pragma unroll
            for (int jt = 0; jt < 7; jt++) {
                uint32_t b0 = bu[jt * 2], b1 = bu[jt * 2 + 1];
                mma_tf32(d[jt], am0, b0, b1);
                mma_tf32(d[7 + jt], am1, b0, b1);
            }
        }
    }
    // epilogue: half2 stores; zero-fill pad cols 50..63
    __half2 z2 = __float2half2_rn(0.f);
    #pragma unroll
    for (int mt = 0; mt < 2; mt++) {
        size_t r0 = rowbase + wid * 32 + mt * 16 + grp;
        __half* p0 = g_u + r0 * USTR;
        #pragma unroll
        for (int jt = 0; jt < 7; jt++) {
            int c0 = jt * 8 + 2 * qid;
            __half2 lo, hi;
            if (jt < 6 || qid == 0) {
                lo = __floats2half2_rn(d[mt * 7 + jt][0], d[mt * 7 + jt][1]);
                hi = __floats2half2_rn(d[mt * 7 + jt][2], d[mt * 7 + jt][3]);
            } else { lo = z2; hi = z2; }
            *(__half2*)(p0 + c0) = lo;
            *(__half2*)(p0 + 8 * USTR + c0) = hi;
        }
        int c0 = 56 + 2 * qid;
        *(__half2*)(p0 + c0) = z2;
        *(__half2*)(p0 + 8 * USTR + c0) = z2;
    }
}

// ---------------- SpMM: warp per (b,n); 2 half-warps x 2 edges, fp16 payload ----
__global__ void __launch_bounds__(256) k_spmm() {
    int gw = blockIdx.x * 8 + (threadIdx.x >> 5);
    int lane = threadIdx.x & 31;
    int b = gw / NNODES;
    int n = gw - b * NNODES;
    const __half* ub = g_u + (size_t)b * (NNODES * USTR);
    int e0 = g_csrptr[n], e1 = g_csrptr[n + 1];
    int grp = lane >> 4, li = lane & 15;
    float ax = 0.f, ay = 0.f, az = 0.f, aw = 0.f;
    int e = e0 + grp;
    for (; e + 2 < e1; e += 4) {
        int s0 = g_csrc[e];     float w0 = g_cw[e];
        int s1 = g_csrc[e + 2]; float w1 = g_cw[e + 2];
        uint2 v0 = *(const uint2*)(ub + (size_t)s0 * USTR + li * 4);
        uint2 v1 = *(const uint2*)(ub + (size_t)s1 * USTR + li * 4);
        float2 p0 = __half22float2(*(__half2*)&v0.x);
        float2 q0 = __half22float2(*(__half2*)&v0.y);
        float2 p1 = __half22float2(*(__half2*)&v1.x);
        float2 q1 = __half22float2(*(__half2*)&v1.y);
        ax += w0 * p0.x + w1 * p1.x;
        ay += w0 * p0.y + w1 * p1.y;
        az += w0 * q0.x + w1 * q1.x;
        aw += w0 * q0.y + w1 * q1.y;
    }
    if (e < e1) {
        int s0 = g_csrc[e]; float w0 = g_cw[e];
        uint2 v0 = *(const uint2*)(ub + (size_t)s0 * USTR + li * 4);
        float2 p0 = __half22float2(*(__half2*)&v0.x);
        float2 q0 = __half22float2(*(__half2*)&v0.y);
        ax += w0 * p0.x; ay += w0 * p0.y;
        az += w0 * q0.x; aw += w0 * q0.y;
    }
    ax += __shfl_xor_sync(0xffffffffu, ax, 16);
    ay += __shfl_xor_sync(0xffffffffu, ay, 16);
    az += __shfl_xor_sync(0xffffffffu, az, 16);
    aw += __shfl_xor_sync(0xffffffffu, aw, 16);
    if (grp == 0 && li < 13) {
        float dv = g_dinv[n];
        float ws = dv * dv;
        uint2 vs = *(const uint2*)(ub + (size_t)n * USTR + li * 4);
        float2 ps = __half22float2(*(__half2*)&vs.x);
        float2 qs = __half22float2(*(__half2*)&vs.y);
        float4 cv = *(const float4*)(g_cvec + li * 4);
        *(float4*)(g_pre + (size_t)gw * HSP + li * 4) = make_float4(
            ax + ws * ps.x + cv.x, ay + ws * ps.y + cv.y,
            az + ws * qs.x + cv.z, aw + ws * qs.y + cv.w);
    }
}

// ---------------- RNN: warp per node, 128 sequential steps ----------------------
__global__ void __launch_bounds__(256) k_rnn(const float* __restrict__ Whh,
                                             const float* __restrict__ bhh,
                                             const float* __restrict__ h0,
                                             float* __restrict__ out) {
    int w = blockIdx.x * 8 + (threadIdx.x >> 5);
    int lane = threadIdx.x & 31;
    if (w >= NNODES) return;
    __shared__ __align__(16) float hsm[8][56];
    float* h = hsm[threadIdx.x >> 5];
    bool hi = lane < 18;
    int c1 = hi ? 32 + lane : 0;
    float w0[HSP], w1[HSP];
    #pragma unroll
    for (int k = 0; k < HS; k++) {
        w0[k] = Whh[lane * HS + k];
        w1[k] = Whh[c1 * HS + k];
    }
    w0[50] = w0[51] = 0.f;
    w1[50] = w1[51] = 0.f;
    float b0 = bhh[lane];
    float b1 = bhh[c1];
    h[lane] = h0[(size_t)w * HS + lane];
    if (hi) h[32 + lane] = h0[(size_t)w * HS + 32 + lane];
    if (lane == 0) { h[50] = 0.f; h[51] = 0.f; }
    __syncwarp();
    const float* prew = g_pre + (size_t)w * HSP;
    float* outw = out + (size_t)w * HS;
    const size_t pstr = (size_t)NNODES * HSP;
    const size_t ostr = (size_t)NNODES * HS;
    float pa0 = prew[lane];
    float pa1 = hi ? prew[32 + lane] : 0.f;
    for (int t = 0; t < NB; t++) {
        float a0 = pa0 + b0;
        float a1 = pa1 + b1;
        if (t + 1 < NB) {
            pa0 = prew[pstr + lane];
            pa1 = hi ? prew[pstr + 32 + lane] : 0.f;
        }
        prew += pstr;
        float s0 = 0.f, s1 = 0.f, s2 = 0.f, s3 = 0.f;
        #pragma unroll
        for (int k = 0; k < HSP; k += 4) {
            float4 hv = *(const float4*)&h[k];
            s0 += hv.x * w0[k]     + hv.y * w0[k + 1];
            s1 += hv.z * w0[k + 2] + hv.w * w0[k + 3];
            s2 += hv.x * w1[k]     + hv.y * w1[k + 1];
            s3 += hv.z * w1[k + 2] + hv.w * w1[k + 3];
        }
        float t0 = tanhf(a0 + s0 + s1);
        float t1 = tanhf(a1 + s2 + s3);
        __syncwarp();
        h[lane] = t0;
        if (hi) h[32 + lane] = t1;
        __syncwarp();
        outw[lane] = t0;
        if (hi) outw[32 + lane] = t1;
        outw += ostr;
    }
}

// ---------------- launch ----------------
extern "C" void kernel_launch(void* const* d_in, const int* in_sizes, int n_in,
                              void* d_out, int out_size) {
    const float* x    = (const float*)d_in[0];
    const void*  eidx = d_in[1];
    const float* ew   = (const float*)d_in[2];
    const float* W    = (const float*)d_in[3];
    const float* b    = (const float*)d_in[4];
    const float* W_ih = (const float*)d_in[5];
    const float* W_hh = (const float*)d_in[6];
    const float* b_ih = (const float*)d_in[7];
    const float* b_hh = (const float*)d_in[8];
    const float* h0   = (const float*)d_in[9];
    float* out = (float*)d_out;

    k_setup<<<33, 256>>>(W, b, W_ih, b_ih);                  // 0
    k_mark<<<(NNODES + 255) / 256, 256>>>(eidx);             // 1
    k_mark2<<<(2 * NEDGES + 255) / 256, 256>>>(eidx);        // 2
    k_gemm<<<NNODES, 128>>>(x);                              // 3  <- profiled
    k_scan<<<1, 1024>>>(0);                                  // 4
    k_edges<<<(NEDGES + 255) / 256, 256>>>(eidx, ew);        // 5
    k_scan<<<1, 1024>>>(1);                                  // 6
    k_fill<<<(NEDGES + 255) / 256, 256>>>(ew);               // 7
    k_spmm<<<(NB * NNODES) / 8, 256>>>();                    // 8
    k_rnn<<<(NNODES + 7) / 8, 256>>>(W_hh, b_hh, h0, out);   // 9
}

// round 7
// speedup vs baseline: 1.4011x; 1.0395x over previous
#include <cuda_runtime.h>
#include <cuda_fp16.h>
#include <math.h>
#include <stdint.h>

#define NNODES 3070
#define NFEAT 128
#define NOUT 64
#define HS 50
#define HSP 52           // fp32 pre row: 52 floats = 13 x float4
#define USTR 64          // fp16 u row: 64 halves = 128B (one cache line)
#define NEDGES 49120
#define NB 128
#define NROWS (NB * NNODES)

// ---------------- device scratch (static, no allocations) ----------------
__device__ int   g_is64;
__device__ int   g_present[NNODES];
__device__ int   g_rank[NNODES];
__device__ float g_deg[NNODES];
__device__ float g_dinv[NNODES];
__device__ int   g_counts[NNODES];
__device__ int   g_csrptr[NNODES + 1];
__device__ int   g_cursor[NNODES];
__device__ int   g_esrc[NEDGES];
__device__ int   g_edst[NEDGES];
__device__ int   g_csrc[NEDGES];
__device__ float g_cw[NEDGES];
// B fragments in mma order: [s(16)][jp(4)][lane(32)][slot(4)] = 32KB
__device__ __align__(16) float g_Bfrag[16 * 4 * 32 * 4];
__device__ __align__(16) float g_cvec[HSP];
__device__ __align__(256) __half g_u[(size_t)NROWS * USTR];
__device__ __align__(16) float g_pre[(size_t)NROWS * HSP];

__device__ __forceinline__ uint32_t to_tf32(float f) {
    uint32_t r;
    asm("cvt.rna.tf32.f32 %0, %1;" : "=r"(r) : "f"(f));
    return r;
}
__device__ __forceinline__ void mma_tf32(float* d, const uint32_t* a,
                                         uint32_t b0, uint32_t b1) {
    asm volatile(
        "mma.sync.aligned.m16n8k8.row.col.f32.tf32.tf32.f32 "
        "{%0,%1,%2,%3}, {%4,%5,%6,%7}, {%8,%9}, {%0,%1,%2,%3};"
        : "+f"(d[0]), "+f"(d[1]), "+f"(d[2]), "+f"(d[3])
        : "r"(a[0]), "r"(a[1]), "r"(a[2]), "r"(a[3]), "r"(b0), "r"(b1));
}
// accurate fast tanh: ex2/rcp approx are ~2^-23 rel err -> ~1e-6 overall
__device__ __forceinline__ float fast_tanh(float x) {
    float e;
    asm("ex2.approx.f32 %0, %1;" : "=f"(e) : "f"(x * 2.8853900817779268f));
    float r;
    asm("rcp.approx.f32 %0, %1;" : "=f"(r) : "f"(e + 1.0f));
    return fmaf(-2.0f, r, 1.0f);
}

// ---------------- setup: B fragments (tf32, K-permuted) + cvec + init -----------
// K permutation: k = 16t + 4q + r -> step = 2t + (r>>1), bidx = r&1, klo = q.
__global__ void k_setup(const void* eidx,
                        const float* __restrict__ W, const float* __restrict__ b,
                        const float* __restrict__ W_ih, const float* __restrict__ b_ih) {
    int i = blockIdx.x * 256 + threadIdx.x;
    if (i == 0) {
        const int* p = (const int*)eidx;
        int is64 = 1;
        for (int j = 1; j < 512; j += 2)
            if (p[j] != 0) { is64 = 0; break; }
        g_is64 = is64;
    }
    if (i < NNODES) {
        g_present[i] = 0; g_deg[i] = 1.0f; g_counts[i] = 0;
    }
    if (i < 128 * 64) {
        int k = i >> 6, c = i & 63;
        float v = 0.f;
        if (c < HS) {
            float s = 0.f;
            #pragma unroll 8
            for (int o = 0; o < NOUT; o++) s += W[k * NOUT + o] * W_ih[c * NOUT + o];
            v = __uint_as_float(to_tf32(s));
        }
        int t16 = k >> 4, j = k & 15, q = j >> 2, r = j & 3;
        int sct = 2 * t16 + (r >> 1);
        int bidx = r & 1;
        int klo = q;
        int jcol = c >> 3, nr = c & 7, jp = jcol >> 1, jodd = jcol & 1;
        int lane = nr * 4 + klo;
        g_Bfrag[(((sct * 4 + jp) * 32 + lane) << 2) + jodd * 2 + bidx] = v;
    }
    int ci = i - 128 * 64;
    if (ci >= 0 && ci < HS) {
        float s = b_ih[ci];
        #pragma unroll 8
        for (int o = 0; o < NOUT; o++) s += b[o] * W_ih[ci * NOUT + o];
        g_cvec[ci] = s;
    }
    if (ci == HS) { g_cvec[50] = 0.f; g_cvec[51] = 0.f; }
}

__device__ __forceinline__ int load_eid(const void* eidx, int i, int is64) {
    if (is64) return (int)((const long long*)eidx)[i];
    return ((const int*)eidx)[i];
}

// ---------------- mark present node ids ----------------
__global__ void k_mark2(const void* eidx) {
    int i = blockIdx.x * 256 + threadIdx.x;
    if (i >= 2 * NEDGES) return;
    g_present[load_eid(eidx, i, g_is64)] = 1;
}

// ---------------- single-block exclusive scans ----------------
__global__ void k_scan(int mode) {
    __shared__ int sa[1024], sb[1024];
    int t = threadIdx.x;
    int base = t * 3;
    const int* in = mode ? g_counts : g_present;
    int v0 = (base     < NNODES) ? in[base]     : 0;
    int v1 = (base + 1 < NNODES) ? in[base + 1] : 0;
    int v2 = (base + 2 < NNODES) ? in[base + 2] : 0;
    int s = v0 + v1 + v2;
    sa[t] = s;
    __syncthreads();
    int* src = sa; int* dst = sb;
    for (int off = 1; off < 1024; off <<= 1) {
        int val = src[t];
        if (t >= off) val += src[t - off];
        dst[t] = val;
        __syncthreads();
        int* tmp = src; src = dst; dst = tmp;
    }
    int incl = src[t];
    int excl = incl - s;
    if (mode == 0) {
        if (base     < NNODES) g_rank[base]     = excl;
        if (base + 1 < NNODES) g_rank[base + 1] = excl + v0;
        if (base + 2 < NNODES) g_rank[base + 2] = excl + v0 + v1;
    } else {
        if (base < NNODES) {
            g_csrptr[base] = excl; g_cursor[base] = excl;
            g_dinv[base] = rsqrtf(g_deg[base]);
        }
        if (base + 1 < NNODES) {
            g_csrptr[base + 1] = excl + v0; g_cursor[base + 1] = excl + v0;
            g_dinv[base + 1] = rsqrtf(g_deg[base + 1]);
        }
        if (base + 2 < NNODES) {
            g_csrptr[base + 2] = excl + v0 + v1; g_cursor[base + 2] = excl + v0 + v1;
            g_dinv[base + 2] = rsqrtf(g_deg[base + 2]);
        }
        if (t == 1023) g_csrptr[NNODES] = incl;
    }
}

// ---------------- remap edges + degree/counts ----------------
__global__ void k_edges(const void* eidx, const float* __restrict__ ew) {
    int e = blockIdx.x * 256 + threadIdx.x;
    if (e >= NEDGES) return;
    int is64 = g_is64;
    int sid = load_eid(eidx, e, is64);
    int did = load_eid(eidx, NEDGES + e, is64);
    int s = g_rank[sid], d = g_rank[did];
    g_esrc[e] = s;
    g_edst[e] = d;
    atomicAdd(&g_deg[d], ew[e]);
    atomicAdd(&g_counts[d], 1);
}

// ---------------- fill CSR (by dst) with normalized weights ----------------
__global__ void k_fill(const float* __restrict__ ew) {
    int e = blockIdx.x * 256 + threadIdx.x;
    if (e >= NEDGES) return;
    int d = g_edst[e], s = g_esrc[e];
    int pos = atomicAdd(&g_cursor[d], 1);
    g_csrc[pos] = s;
    g_cw[pos] = g_dinv[s] * ew[e] * g_dinv[d];
}

// ---------------- GEMM: u = x @ M via mma.sync tf32 m16n8k8, fp16 out -----------
__global__ void __launch_bounds__(128) k_gemm(const float* __restrict__ x) {
    __shared__ __align__(16) float4 Bs[16 * 4 * 32];
    int tid = threadIdx.x, wid = tid >> 5, lane = tid & 31;
    {
        const float4* s = (const float4*)g_Bfrag;
        #pragma unroll
        for (int i = 0; i < 16; i++) Bs[tid + 128 * i] = s[tid + 128 * i];
    }
    size_t rowbase = (size_t)blockIdx.x * 128;
    int grp = lane >> 2, qid = lane & 3;
    const float* px = x + (rowbase + wid * 32 + grp) * NFEAT + 4 * qid;
    __syncthreads();

    float d[14][4];
    #pragma unroll
    for (int i = 0; i < 14; i++)
        #pragma unroll
        for (int j = 0; j < 4; j++) d[i][j] = 0.f;

    #pragma unroll
    for (int t = 0; t < 8; t++) {
        float4 v0 = *(const float4*)(px + 16 * t);
        float4 v1 = *(const float4*)(px + 8 * NFEAT + 16 * t);
        float4 v2 = *(const float4*)(px + 16 * NFEAT + 16 * t);
        float4 v3 = *(const float4*)(px + 24 * NFEAT + 16 * t);
        #pragma unroll
        for (int ss = 0; ss < 2; ss++) {
            int s = 2 * t + ss;
            uint32_t am0[4], am1[4];
            if (ss == 0) {
                am0[0] = to_tf32(v0.x); am0[1] = to_tf32(v1.x);
                am0[2] = to_tf32(v0.y); am0[3] = to_tf32(v1.y);
                am1[0] = to_tf32(v2.x); am1[1] = to_tf32(v3.x);
                am1[2] = to_tf32(v2.y); am1[3] = to_tf32(v3.y);
            } else {
                am0[0] = to_tf32(v0.z); am0[1] = to_tf32(v1.z);
                am0[2] = to_tf32(v0.w); am0[3] = to_tf32(v1.w);
                am1[0] = to_tf32(v2.z); am1[1] = to_tf32(v3.z);
                am1[2] = to_tf32(v2.w); am1[3] = to_tf32(v3.w);
            }
            float4 bv[4];
            #pragma unroll
            for (int jp = 0; jp < 4; jp++) bv[jp] = Bs[(s * 4 + jp) * 32 + lane];
            const uint32_t* bu = (const uint32_t*)bv;
            #pragma unroll
            for (int jt = 0; jt < 7; jt++) {
                uint32_t b0 = bu[jt * 2], b1 = bu[jt * 2 + 1];
                mma_tf32(d[jt], am0, b0, b1);
                mma_tf32(d[7 + jt], am1, b0, b1);
            }
        }
    }
    __half2 z2 = __float2half2_rn(0.f);
    #pragma unroll
    for (int mt = 0; mt < 2; mt++) {
        size_t r0 = rowbase + wid * 32 + mt * 16 + grp;
        __half* p0 = g_u + r0 * USTR;
        #pragma unroll
        for (int jt = 0; jt < 7; jt++) {
            int c0 = jt * 8 + 2 * qid;
            __half2 lo, hi;
            if (jt < 6 || qid == 0) {
                lo = __floats2half2_rn(d[mt * 7 + jt][0], d[mt * 7 + jt][1]);
                hi = __floats2half2_rn(d[mt * 7 + jt][2], d[mt * 7 + jt][3]);
            } else { lo = z2; hi = z2; }
            *(__half2*)(p0 + c0) = lo;
            *(__half2*)(p0 + 8 * USTR + c0) = hi;
        }
        int c0 = 56 + 2 * qid;
        *(__half2*)(p0 + c0) = z2;
        *(__half2*)(p0 + 8 * USTR + c0) = z2;
    }
}

// ---------------- SpMM: CTA per (node, 8-batch group); smem-staged edges --------
// 8 warps/CTA, warp w -> batch bg*8+w; 2 half-warps per warp process alternating
// edges; lanes hold 4 halves each (64-half row); shfl reduce; lanes 0..12 store.
__global__ void __launch_bounds__(256) k_spmm() {
    __shared__ __align__(8) float2 sedge[256];
    int n = blockIdx.x >> 4;
    int bg = blockIdx.x & 15;
    int tid = threadIdx.x;
    int wid = tid >> 5, lane = tid & 31;
    int grp = lane >> 4, li = lane & 15;
    int b = bg * 8 + wid;
    const __half* ulane = g_u + (size_t)b * (NNODES * USTR) + li * 4;
    int e0 = g_csrptr[n], e1 = g_csrptr[n + 1];
    float ax = 0.f, ay = 0.f, az = 0.f, aw = 0.f;
    for (int base = e0; base < e1; base += 256) {
        int m = min(256, e1 - base);
        __syncthreads();
        if (tid < m)
            sedge[tid] = make_float2(g_cw[base + tid],
                                     __int_as_float(g_csrc[base + tid]));
        __syncthreads();
        int j = grp;
        for (; j + 2 < m; j += 4) {
            float2 p0 = sedge[j], p1 = sedge[j + 2];
            int s0 = __float_as_int(p0.y), s1 = __float_as_int(p1.y);
            uint2 v0 = *(const uint2*)(ulane + (size_t)s0 * USTR);
            uint2 v1 = *(const uint2*)(ulane + (size_t)s1 * USTR);
            float2 a0 = __half22float2(*(__half2*)&v0.x);
            float2 c0 = __half22float2(*(__half2*)&v0.y);
            float2 a1 = __half22float2(*(__half2*)&v1.x);
            float2 c1 = __half22float2(*(__half2*)&v1.y);
            ax += p0.x * a0.x + p1.x * a1.x;
            ay += p0.x * a0.y + p1.x * a1.y;
            az += p0.x * c0.x + p1.x * c1.x;
            aw += p0.x * c0.y + p1.x * c1.y;
        }
        if (j < m) {
            float2 p0 = sedge[j];
            int s0 = __float_as_int(p0.y);
            uint2 v0 = *(const uint2*)(ulane + (size_t)s0 * USTR);
            float2 a0 = __half22float2(*(__half2*)&v0.x);
            float2 c0 = __half22float2(*(__half2*)&v0.y);
            ax += p0.x * a0.x; ay += p0.x * a0.y;
            az += p0.x * c0.x; aw += p0.x * c0.y;
        }
    }
    ax += __shfl_xor_sync(0xffffffffu, ax, 16);
    ay += __shfl_xor_sync(0xffffffffu, ay, 16);
    az += __shfl_xor_sync(0xffffffffu, az, 16);
    aw += __shfl_xor_sync(0xffffffffu, aw, 16);
    if (grp == 0 && li < 13) {
        float dv = g_dinv[n];
        float ws = dv * dv;
        uint2 vs = *(const uint2*)(ulane + (size_t)n * USTR);
        float2 ps = __half22float2(*(__half2*)&vs.x);
        float2 qs = __half22float2(*(__half2*)&vs.y);
        float4 cv = *(const float4*)(g_cvec + li * 4);
        *(float4*)(g_pre + ((size_t)b * NNODES + n) * HSP + li * 4) = make_float4(
            ax + ws * ps.x + cv.x, ay + ws * ps.y + cv.y,
            az + ws * qs.x + cv.z, aw + ws * qs.y + cv.w);
    }
}

// ---------------- RNN: warp per node, 128 sequential steps ----------------------
__global__ void __launch_bounds__(256) k_rnn(const float* __restrict__ Whh,
                                             const float* __restrict__ bhh,
                                             const float* __restrict__ h0,
                                             float* __restrict__ out) {
    int w = blockIdx.x * 8 + (threadIdx.x >> 5);
    int lane = threadIdx.x & 31;
    if (w >= NNODES) return;
    __shared__ __align__(16) float hsm[8][56];
    float* h = hsm[threadIdx.x >> 5];
    bool hi = lane < 18;
    int c1 = hi ? 32 + lane : 0;
    float w0[HSP], w1[HSP];
    #pragma unroll
    for (int k = 0; k < HS; k++) {
        w0[k] = Whh[lane * HS + k];
        w1[k] = Whh[c1 * HS + k];
    }
    w0[50] = w0[51] = 0.f;
    w1[50] = w1[51] = 0.f;
    float b0 = bhh[lane];
    float b1 = bhh[c1];
    h[lane] = h0[(size_t)w * HS + lane];
    if (hi) h[32 + lane] = h0[(size_t)w * HS + 32 + lane];
    if (lane == 0) { h[50] = 0.f; h[51] = 0.f; }
    __syncwarp();
    const float* prew = g_pre + (size_t)w * HSP;
    float* outw = out + (size_t)w * HS;
    const size_t pstr = (size_t)NNODES * HSP;
    const size_t ostr = (size_t)NNODES * HS;
    float pa0 = prew[lane];
    float pa1 = hi ? prew[32 + lane] : 0.f;
    for (int t = 0; t < NB; t++) {
        float a0 = pa0 + b0;
        float a1 = pa1 + b1;
        if (t + 1 < NB) {
            pa0 = prew[pstr + lane];
            pa1 = hi ? prew[pstr + 32 + lane] : 0.f;
        }
        prew += pstr;
        float s0 = 0.f, s1 = 0.f, s2 = 0.f, s3 = 0.f;
        #pragma unroll
        for (int k = 0; k < HSP; k += 4) {
            float4 hv = *(const float4*)&h[k];
            s0 += hv.x * w0[k]     + hv.y * w0[k + 1];
            s1 += hv.z * w0[k + 2] + hv.w * w0[k + 3];
            s2 += hv.x * w1[k]     + hv.y * w1[k + 1];
            s3 += hv.z * w1[k + 2] + hv.w * w1[k + 3];
        }
        float t0 = fast_tanh(a0 + s0 + s1);
        float t1 = fast_tanh(a1 + s2 + s3);
        __syncwarp();
        h[lane] = t0;
        if (hi) h[32 + lane] = t1;
        __syncwarp();
        outw[lane] = t0;
        if (hi) outw[32 + lane] = t1;
        outw += ostr;
    }
}

// ---------------- launch ----------------
extern "C" void kernel_launch(void* const* d_in, const int* in_sizes, int n_in,
                              void* d_out, int out_size) {
    const float* x    = (const float*)d_in[0];
    const void*  eidx = d_in[1];
    const float* ew   = (const float*)d_in[2];
    const float* W    = (const float*)d_in[3];
    const float* b    = (const float*)d_in[4];
    const float* W_ih = (const float*)d_in[5];
    const float* W_hh = (const float*)d_in[6];
    const float* b_ih = (const float*)d_in[7];
    const float* b_hh = (const float*)d_in[8];
    const float* h0   = (const float*)d_in[9];
    float* out = (float*)d_out;

    k_setup<<<33, 256>>>(eidx, W, b, W_ih, b_ih);            // 0
    k_mark2<<<(2 * NEDGES + 255) / 256, 256>>>(eidx);        // 1
    k_scan<<<1, 1024>>>(0);                                  // 2
    k_gemm<<<NNODES, 128>>>(x);                              // 3  <- profiled
    k_edges<<<(NEDGES + 255) / 256, 256>>>(eidx, ew);        // 4
    k_scan<<<1, 1024>>>(1);                                  // 5
    k_fill<<<(NEDGES + 255) / 256, 256>>>(ew);               // 6
    k_spmm<<<NNODES * 16, 256>>>();                          // 7
    k_rnn<<<(NNODES + 7) / 8, 256>>>(W_hh, b_hh, h0, out);   // 8
}

// round 8
// speedup vs baseline: 1.5272x; 1.0900x over previous
#include <cuda_runtime.h>
#include <cuda_fp16.h>
#include <math.h>
#include <stdint.h>

#define NNODES 3070
#define NFEAT 128
#define NOUT 64
#define HS 50
#define HSP 52           // fp32 pre row: 52 floats = 13 x float4
#define USTR 64          // fp16 u row: 64 halves = 128B (one cache line)
#define NEDGES 49120
#define NB 128
#define NROWS (NB * NNODES)

// ---------------- device scratch (static, no allocations) ----------------
__device__ int   g_is64;
__device__ int   g_present[NNODES];   // idempotent marks; never re-zeroed
__device__ int   g_rank[NNODES];
__device__ float g_deg[NNODES];
__device__ float g_dinv[NNODES];
__device__ int   g_counts[NNODES];
__device__ int   g_csrptr[NNODES + 1];
__device__ int   g_cursor[NNODES];
__device__ int   g_esrc[NEDGES];
__device__ int   g_edst[NEDGES];
__device__ int   g_csrc[NEDGES];
__device__ float g_cw[NEDGES];
// B fragments in mma order: [s(16)][jp(4)][lane(32)][slot(4)] = 32KB
__device__ __align__(16) float g_Bfrag[16 * 4 * 32 * 4];
__device__ __align__(16) float g_cvec[HSP];
__device__ __align__(256) __half g_u[(size_t)NROWS * USTR];
__device__ __align__(16) float g_pre[(size_t)NROWS * HSP];

__device__ __forceinline__ uint32_t to_tf32(float f) {
    uint32_t r;
    asm("cvt.rna.tf32.f32 %0, %1;" : "=r"(r) : "f"(f));
    return r;
}
__device__ __forceinline__ void mma_tf32(float* d, const uint32_t* a,
                                         uint32_t b0, uint32_t b1) {
    asm volatile(
        "mma.sync.aligned.m16n8k8.row.col.f32.tf32.tf32.f32 "
        "{%0,%1,%2,%3}, {%4,%5,%6,%7}, {%8,%9}, {%0,%1,%2,%3};"
        : "+f"(d[0]), "+f"(d[1]), "+f"(d[2]), "+f"(d[3])
        : "r"(a[0]), "r"(a[1]), "r"(a[2]), "r"(a[3]), "r"(b0), "r"(b1));
}
// accurate fast tanh: ex2/rcp approx are ~2^-23 rel err -> ~1e-6 overall
__device__ __forceinline__ float fast_tanh(float x) {
    float e;
    asm("ex2.approx.f32 %0, %1;" : "=f"(e) : "f"(x * 2.8853900817779268f));
    float r;
    asm("rcp.approx.f32 %0, %1;" : "=f"(r) : "f"(e + 1.0f));
    return fmaf(-2.0f, r, 1.0f);
}

__device__ __forceinline__ int load_eid(const void* eidx, int i, int is64) {
    if (is64) return (int)((const long long*)eidx)[i];
    return ((const int*)eidx)[i];
}

// ---------------- setup: mark + init + B fragments + cvec -----------------------
// K permutation: k = 16t + 4q + r -> step = 2t + (r>>1), bidx = r&1, klo = q.
__global__ void k_setup(const void* eidx,
                        const float* __restrict__ W, const float* __restrict__ b,
                        const float* __restrict__ W_ih, const float* __restrict__ b_ih) {
    // per-block dtype detect (cheap, no cross-kernel dependency)
    const int* p = (const int*)eidx;
    int is64 = 1;
    for (int j = 1; j < 512; j += 2)
        if (p[j] != 0) { is64 = 0; break; }
    int i = blockIdx.x * 256 + threadIdx.x;
    if (i == 0) g_is64 = is64;
    if (i < 2 * NEDGES) g_present[load_eid(eidx, i, is64)] = 1;
    if (i < NNODES) { g_deg[i] = 1.0f; g_counts[i] = 0; }
    if (i < 128 * 64) {
        int k = i >> 6, c = i & 63;
        float v = 0.f;
        if (c < HS) {
            float s = 0.f;
            #pragma unroll 8
            for (int o = 0; o < NOUT; o++) s += W[k * NOUT + o] * W_ih[c * NOUT + o];
            v = __uint_as_float(to_tf32(s));
        }
        int t16 = k >> 4, j = k & 15, q = j >> 2, r = j & 3;
        int sct = 2 * t16 + (r >> 1);
        int bidx = r & 1;
        int klo = q;
        int jcol = c >> 3, nr = c & 7, jp = jcol >> 1, jodd = jcol & 1;
        int lane = nr * 4 + klo;
        g_Bfrag[(((sct * 4 + jp) * 32 + lane) << 2) + jodd * 2 + bidx] = v;
    }
    int ci = i - 128 * 64;
    if (ci >= 0 && ci < HS) {
        float s = b_ih[ci];
        #pragma unroll 8
        for (int o = 0; o < NOUT; o++) s += b[o] * W_ih[ci * NOUT + o];
        g_cvec[ci] = s;
    }
    if (ci == HS) { g_cvec[50] = 0.f; g_cvec[51] = 0.f; }
}

// ---------------- single-block exclusive scans ----------------
__global__ void k_scan(int mode) {
    __shared__ int sa[1024], sb[1024];
    int t = threadIdx.x;
    int base = t * 3;
    const int* in = mode ? g_counts : g_present;
    int v0 = (base     < NNODES) ? in[base]     : 0;
    int v1 = (base + 1 < NNODES) ? in[base + 1] : 0;
    int v2 = (base + 2 < NNODES) ? in[base + 2] : 0;
    int s = v0 + v1 + v2;
    sa[t] = s;
    __syncthreads();
    int* src = sa; int* dst = sb;
    for (int off = 1; off < 1024; off <<= 1) {
        int val = src[t];
        if (t >= off) val += src[t - off];
        dst[t] = val;
        __syncthreads();
        int* tmp = src; src = dst; dst = tmp;
    }
    int incl = src[t];
    int excl = incl - s;
    if (mode == 0) {
        if (base     < NNODES) g_rank[base]     = excl;
        if (base + 1 < NNODES) g_rank[base + 1] = excl + v0;
        if (base + 2 < NNODES) g_rank[base + 2] = excl + v0 + v1;
    } else {
        if (base < NNODES) {
            g_csrptr[base] = excl; g_cursor[base] = excl;
            g_dinv[base] = rsqrtf(g_deg[base]);
        }
        if (base + 1 < NNODES) {
            g_csrptr[base + 1] = excl + v0; g_cursor[base + 1] = excl + v0;
            g_dinv[base + 1] = rsqrtf(g_deg[base + 1]);
        }
        if (base + 2 < NNODES) {
            g_csrptr[base + 2] = excl + v0 + v1; g_cursor[base + 2] = excl + v0 + v1;
            g_dinv[base + 2] = rsqrtf(g_deg[base + 2]);
        }
        if (t == 1023) g_csrptr[NNODES] = incl;
    }
}

// ---------------- remap edges + degree/counts ----------------
__global__ void k_edges(const void* eidx, const float* __restrict__ ew) {
    int e = blockIdx.x * 256 + threadIdx.x;
    if (e >= NEDGES) return;
    int is64 = g_is64;
    int sid = load_eid(eidx, e, is64);
    int did = load_eid(eidx, NEDGES + e, is64);
    int s = g_rank[sid], d = g_rank[did];
    g_esrc[e] = s;
    g_edst[e] = d;
    atomicAdd(&g_deg[d], ew[e]);
    atomicAdd(&g_counts[d], 1);
}

// ---------------- fill CSR (by dst) with normalized weights ----------------
__global__ void k_fill(const float* __restrict__ ew) {
    int e = blockIdx.x * 256 + threadIdx.x;
    if (e >= NEDGES) return;
    int d = g_edst[e], s = g_esrc[e];
    int pos = atomicAdd(&g_cursor[d], 1);
    g_csrc[pos] = s;
    g_cw[pos] = g_dinv[s] * ew[e] * g_dinv[d];
}

// ---------------- GEMM: u = x @ M via mma.sync tf32 m16n8k8, fp16 out -----------
__global__ void __launch_bounds__(128) k_gemm(const float* __restrict__ x) {
    __shared__ __align__(16) float4 Bs[16 * 4 * 32];
    int tid = threadIdx.x, wid = tid >> 5, lane = tid & 31;
    {
        const float4* s = (const float4*)g_Bfrag;
        #pragma unroll
        for (int i = 0; i < 16; i++) Bs[tid + 128 * i] = s[tid + 128 * i];
    }
    size_t rowbase = (size_t)blockIdx.x * 128;
    int grp = lane >> 2, qid = lane & 3;
    const float* px = x + (rowbase + wid * 32 + grp) * NFEAT + 4 * qid;
    __syncthreads();

    float d[14][4];
    #pragma unroll
    for (int i = 0; i < 14; i++)
        #pragma unroll
        for (int j = 0; j < 4; j++) d[i][j] = 0.f;

    #pragma unroll
    for (int t = 0; t < 8; t++) {
        float4 v0 = *(const float4*)(px + 16 * t);
        float4 v1 = *(const float4*)(px + 8 * NFEAT + 16 * t);
        float4 v2 = *(const float4*)(px + 16 * NFEAT + 16 * t);
        float4 v3 = *(const float4*)(px + 24 * NFEAT + 16 * t);
        #pragma unroll
        for (int ss = 0; ss < 2; ss++) {
            int s = 2 * t + ss;
            uint32_t am0[4], am1[4];
            if (ss == 0) {
                am0[0] = to_tf32(v0.x); am0[1] = to_tf32(v1.x);
                am0[2] = to_tf32(v0.y); am0[3] = to_tf32(v1.y);
                am1[0] = to_tf32(v2.x); am1[1] = to_tf32(v3.x);
                am1[2] = to_tf32(v2.y); am1[3] = to_tf32(v3.y);
            } else {
                am0[0] = to_tf32(v0.z); am0[1] = to_tf32(v1.z);
                am0[2] = to_tf32(v0.w); am0[3] = to_tf32(v1.w);
                am1[0] = to_tf32(v2.z); am1[1] = to_tf32(v3.z);
                am1[2] = to_tf32(v2.w); am1[3] = to_tf32(v3.w);
            }
            float4 bv[4];
            #pragma unroll
            for (int jp = 0; jp < 4; jp++) bv[jp] = Bs[(s * 4 + jp) * 32 + lane];
            const uint32_t* bu = (const uint32_t*)bv;
            #pragma unroll
            for (int jt = 0; jt < 7; jt++) {
                uint32_t b0 = bu[jt * 2], b1 = bu[jt * 2 + 1];
                mma_tf32(d[jt], am0, b0, b1);
                mma_tf32(d[7 + jt], am1, b0, b1);
            }
        }
    }
    __half2 z2 = __float2half2_rn(0.f);
    #pragma unroll
    for (int mt = 0; mt < 2; mt++) {
        size_t r0 = rowbase + wid * 32 + mt * 16 + grp;
        __half* p0 = g_u + r0 * USTR;
        #pragma unroll
        for (int jt = 0; jt < 7; jt++) {
            int c0 = jt * 8 + 2 * qid;
            __half2 lo, hi;
            if (jt < 6 || qid == 0) {
                lo = __floats2half2_rn(d[mt * 7 + jt][0], d[mt * 7 + jt][1]);
                hi = __floats2half2_rn(d[mt * 7 + jt][2], d[mt * 7 + jt][3]);
            } else { lo = z2; hi = z2; }
            *(__half2*)(p0 + c0) = lo;
            *(__half2*)(p0 + 8 * USTR + c0) = hi;
        }
        int c0 = 56 + 2 * qid;
        *(__half2*)(p0 + c0) = z2;
        *(__half2*)(p0 + 8 * USTR + c0) = z2;
    }
}

// ---------------- SpMM: warp per (n,b), n-major (CTA shares node's edges) -------
// 2 half-warps process alternating edges; 16 lanes x uint2 = one 128B line.
__global__ void __launch_bounds__(256) k_spmm() {
    int gw = blockIdx.x * 8 + (threadIdx.x >> 5);
    int lane = threadIdx.x & 31;
    int n = gw >> 7;          // 128 batches per node, same n across CTA
    int b = gw & 127;
    const __half* ub = g_u + (size_t)b * (NNODES * USTR);
    int e0 = g_csrptr[n], e1 = g_csrptr[n + 1];
    int grp = lane >> 4, li = lane & 15;
    float ax = 0.f, ay = 0.f, az = 0.f, aw = 0.f;
    int e = e0 + grp;
    for (; e + 2 < e1; e += 4) {
        int s0 = g_csrc[e];     float w0 = g_cw[e];
        int s1 = g_csrc[e + 2]; float w1 = g_cw[e + 2];
        uint2 v0 = *(const uint2*)(ub + (size_t)s0 * USTR + li * 4);
        uint2 v1 = *(const uint2*)(ub + (size_t)s1 * USTR + li * 4);
        float2 p0 = __half22float2(*(__half2*)&v0.x);
        float2 q0 = __half22float2(*(__half2*)&v0.y);
        float2 p1 = __half22float2(*(__half2*)&v1.x);
        float2 q1 = __half22float2(*(__half2*)&v1.y);
        ax += w0 * p0.x + w1 * p1.x;
        ay += w0 * p0.y + w1 * p1.y;
        az += w0 * q0.x + w1 * q1.x;
        aw += w0 * q0.y + w1 * q1.y;
    }
    if (e < e1) {
        int s0 = g_csrc[e]; float w0 = g_cw[e];
        uint2 v0 = *(const uint2*)(ub + (size_t)s0 * USTR + li * 4);
        float2 p0 = __half22float2(*(__half2*)&v0.x);
        float2 q0 = __half22float2(*(__half2*)&v0.y);
        ax += w0 * p0.x; ay += w0 * p0.y;
        az += w0 * q0.x; aw += w0 * q0.y;
    }
    ax += __shfl_xor_sync(0xffffffffu, ax, 16);
    ay += __shfl_xor_sync(0xffffffffu, ay, 16);
    az += __shfl_xor_sync(0xffffffffu, az, 16);
    aw += __shfl_xor_sync(0xffffffffu, aw, 16);
    if (grp == 0 && li < 13) {
        float dv = g_dinv[n];
        float ws = dv * dv;
        uint2 vs = *(const uint2*)(ub + (size_t)n * USTR + li * 4);
        float2 ps = __half22float2(*(__half2*)&vs.x);
        float2 qs = __half22float2(*(__half2*)&vs.y);
        float4 cv = *(const float4*)(g_cvec + li * 4);
        *(float4*)(g_pre + ((size_t)b * NNODES + n) * HSP + li * 4) = make_float4(
            ax + ws * ps.x + cv.x, ay + ws * ps.y + cv.y,
            az + ws * qs.x + cv.z, aw + ws * qs.y + cv.w);
    }
}

// ---------------- RNN: warp per node, 128 steps, double-buffered h --------------
__global__ void __launch_bounds__(256) k_rnn(const float* __restrict__ Whh,
                                             const float* __restrict__ bhh,
                                             const float* __restrict__ h0,
                                             float* __restrict__ out) {
    int w = blockIdx.x * 8 + (threadIdx.x >> 5);
    int lane = threadIdx.x & 31;
    if (w >= NNODES) return;
    __shared__ __align__(16) float hsm[8][2][56];
    float* hc = hsm[threadIdx.x >> 5][0];
    float* hn = hsm[threadIdx.x >> 5][1];
    bool hi = lane < 18;
    int c1 = hi ? 32 + lane : 0;
    float w0[HSP], w1[HSP];
    #pragma unroll
    for (int k = 0; k < HS; k++) {
        w0[k] = Whh[lane * HS + k];
        w1[k] = Whh[c1 * HS + k];
    }
    w0[50] = w0[51] = 0.f;
    w1[50] = w1[51] = 0.f;
    float b0 = bhh[lane];
    float b1 = bhh[c1];
    hc[lane] = h0[(size_t)w * HS + lane];
    if (hi) hc[32 + lane] = h0[(size_t)w * HS + 32 + lane];
    if (lane == 0) { hc[50] = 0.f; hc[51] = 0.f; hn[50] = 0.f; hn[51] = 0.f; }
    __syncwarp();
    const float* prew = g_pre + (size_t)w * HSP;
    float* outw = out + (size_t)w * HS;
    const size_t pstr = (size_t)NNODES * HSP;
    const size_t ostr = (size_t)NNODES * HS;
    float pa0 = prew[lane];
    float pa1 = hi ? prew[32 + lane] : 0.f;
    for (int t = 0; t < NB; t++) {
        float a0 = pa0 + b0;
        float a1 = pa1 + b1;
        if (t + 1 < NB) {
            pa0 = prew[pstr + lane];
            pa1 = hi ? prew[pstr + 32 + lane] : 0.f;
        }
        prew += pstr;
        float s0 = 0.f, s1 = 0.f, s2 = 0.f, s3 = 0.f;
        #pragma unroll
        for (int k = 0; k < HSP; k += 4) {
            float4 hv = *(const float4*)&hc[k];
            s0 += hv.x * w0[k]     + hv.y * w0[k + 1];
            s1 += hv.z * w0[k + 2] + hv.w * w0[k + 3];
            s2 += hv.x * w1[k]     + hv.y * w1[k + 1];
            s3 += hv.z * w1[k + 2] + hv.w * w1[k + 3];
        }
        float t0 = fast_tanh(a0 + s0 + s1);
        float t1 = fast_tanh(a1 + s2 + s3);
        hn[lane] = t0;
        if (hi) hn[32 + lane] = t1;
        __syncwarp();
        float* tmp = hc; hc = hn; hn = tmp;
        outw[lane] = t0;
        if (hi) outw[32 + lane] = t1;
        outw += ostr;
    }
}

// ---------------- launch ----------------
extern "C" void kernel_launch(void* const* d_in, const int* in_sizes, int n_in,
                              void* d_out, int out_size) {
    const float* x    = (const float*)d_in[0];
    const void*  eidx = d_in[1];
    const float* ew   = (const float*)d_in[2];
    const float* W    = (const float*)d_in[3];
    const float* b    = (const float*)d_in[4];
    const float* W_ih = (const float*)d_in[5];
    const float* W_hh = (const float*)d_in[6];
    const float* b_ih = (const float*)d_in[7];
    const float* b_hh = (const float*)d_in[8];
    const float* h0   = (const float*)d_in[9];
    float* out = (float*)d_out;

    k_setup<<<(2 * NEDGES + 255) / 256, 256>>>(eidx, W, b, W_ih, b_ih);  // 0
    k_scan<<<1, 1024>>>(0);                                  // 1
    k_edges<<<(NEDGES + 255) / 256, 256>>>(eidx, ew);        // 2
    k_scan<<<1, 1024>>>(1);                                  // 3  <- profiled
    k_fill<<<(NEDGES + 255) / 256, 256>>>(ew);               // 4
    k_gemm<<<NNODES, 128>>>(x);                              // 5
    k_spmm<<<(NB * NNODES) / 8, 256>>>();                    // 6
    k_rnn<<<(NNODES + 7) / 8, 256>>>(W_hh, b_hh, h0, out);   // 7
}

// round 9
// speedup vs baseline: 1.6830x; 1.1020x over previous
#include <cuda_runtime.h>
#include <cuda_fp16.h>
#include <math.h>
#include <stdint.h>

#define NNODES 3070
#define NFEAT 128
#define NOUT 64
#define HS 50
#define HSP 52           // fp32 pre row: 52 floats = 13 x float4
#define USTR 64          // fp16 u row: 64 halves = 128B (one cache line)
#define NEDGES 49120
#define NB 128
#define NROWS (NB * NNODES)

// ---------------- device scratch (static, no allocations) ----------------
__device__ int   g_is64;
__device__ int   g_present[NNODES];   // idempotent marks; never re-zeroed
__device__ int   g_rank[NNODES];
__device__ float g_deg[NNODES];
__device__ float g_dinv[NNODES];
__device__ int   g_counts[NNODES];
__device__ int   g_csrptr[NNODES + 1];
__device__ int   g_cursor[NNODES];
__device__ int   g_esrc[NEDGES];
__device__ int   g_edst[NEDGES];
__device__ int   g_csrc[NEDGES];
__device__ float g_cw[NEDGES];
// B fragments in mma order: [s(16)][jp(4)][lane(32)][slot(4)] = 32KB
__device__ __align__(16) float g_Bfrag[16 * 4 * 32 * 4];
__device__ __align__(16) float g_cvec[HSP];
__device__ __align__(256) __half g_u[(size_t)NROWS * USTR];
__device__ __align__(16) float g_pre[(size_t)NROWS * HSP];

__device__ __forceinline__ uint32_t to_tf32(float f) {
    uint32_t r;
    asm("cvt.rna.tf32.f32 %0, %1;" : "=r"(r) : "f"(f));
    return r;
}
__device__ __forceinline__ void mma_tf32(float* d, const uint32_t* a,
                                         uint32_t b0, uint32_t b1) {
    asm volatile(
        "mma.sync.aligned.m16n8k8.row.col.f32.tf32.tf32.f32 "
        "{%0,%1,%2,%3}, {%4,%5,%6,%7}, {%8,%9}, {%0,%1,%2,%3};"
        : "+f"(d[0]), "+f"(d[1]), "+f"(d[2]), "+f"(d[3])
        : "r"(a[0]), "r"(a[1]), "r"(a[2]), "r"(a[3]), "r"(b0), "r"(b1));
}
// accurate fast tanh: ex2/rcp approx are ~2^-23 rel err -> ~1e-6 overall
__device__ __forceinline__ float fast_tanh(float x) {
    float e;
    asm("ex2.approx.f32 %0, %1;" : "=f"(e) : "f"(x * 2.8853900817779268f));
    float r;
    asm("rcp.approx.f32 %0, %1;" : "=f"(r) : "f"(e + 1.0f));
    return fmaf(-2.0f, r, 1.0f);
}
// packed f32x2 fma (Blackwell FFMA2, base sm_100+ feature)
__device__ __forceinline__ unsigned long long fma2(unsigned long long a,
                                                   unsigned long long b,
                                                   unsigned long long c) {
    unsigned long long d;
    asm("fma.rn.f32x2 %0, %1, %2, %3;" : "=l"(d) : "l"(a), "l"(b), "l"(c));
    return d;
}
__device__ __forceinline__ unsigned long long pk2(float x, float y) {
    unsigned long long r;
    asm("mov.b64 %0, {%1, %2};" : "=l"(r) : "f"(x), "f"(y));
    return r;
}
__device__ __forceinline__ float2 upk2(unsigned long long v) {
    float2 r;
    asm("mov.b64 {%0, %1}, %2;" : "=f"(r.x), "=f"(r.y) : "l"(v));
    return r;
}

__device__ __forceinline__ int load_eid(const void* eidx, int i, int is64) {
    if (is64) return (int)((const long long*)eidx)[i];
    return ((const int*)eidx)[i];
}

// ---------------- setup: mark + init + B fragments + cvec -----------------------
// K permutation: k = 16t + 4q + r -> step = 2t + (r>>1), bidx = r&1, klo = q.
__global__ void k_setup(const void* eidx,
                        const float* __restrict__ W, const float* __restrict__ b,
                        const float* __restrict__ W_ih, const float* __restrict__ b_ih) {
    const int* p = (const int*)eidx;
    int is64 = 1;
    for (int j = 1; j < 512; j += 2)
        if (p[j] != 0) { is64 = 0; break; }
    int i = blockIdx.x * 256 + threadIdx.x;
    if (i == 0) g_is64 = is64;
    if (i < 2 * NEDGES) g_present[load_eid(eidx, i, is64)] = 1;
    if (i < NNODES) { g_deg[i] = 1.0f; g_counts[i] = 0; }
    if (i < 128 * 64) {
        int k = i >> 6, c = i & 63;
        float v = 0.f;
        if (c < HS) {
            float s = 0.f;
            #pragma unroll 8
            for (int o = 0; o < NOUT; o++) s += W[k * NOUT + o] * W_ih[c * NOUT + o];
            v = __uint_as_float(to_tf32(s));
        }
        int t16 = k >> 4, j = k & 15, q = j >> 2, r = j & 3;
        int sct = 2 * t16 + (r >> 1);
        int bidx = r & 1;
        int klo = q;
        int jcol = c >> 3, nr = c & 7, jp = jcol >> 1, jodd = jcol & 1;
        int lane = nr * 4 + klo;
        g_Bfrag[(((sct * 4 + jp) * 32 + lane) << 2) + jodd * 2 + bidx] = v;
    }
    int ci = i - 128 * 64;
    if (ci >= 0 && ci < HS) {
        float s = b_ih[ci];
        #pragma unroll 8
        for (int o = 0; o < NOUT; o++) s += b[o] * W_ih[ci * NOUT + o];
        g_cvec[ci] = s;
    }
    if (ci == HS) { g_cvec[50] = 0.f; g_cvec[51] = 0.f; }
}

// ---------------- single-block exclusive scans ----------------
__global__ void k_scan(int mode) {
    __shared__ int sa[1024], sb[1024];
    int t = threadIdx.x;
    int base = t * 3;
    const int* in = mode ? g_counts : g_present;
    int v0 = (base     < NNODES) ? in[base]     : 0;
    int v1 = (base + 1 < NNODES) ? in[base + 1] : 0;
    int v2 = (base + 2 < NNODES) ? in[base + 2] : 0;
    int s = v0 + v1 + v2;
    sa[t] = s;
    __syncthreads();
    int* src = sa; int* dst = sb;
    for (int off = 1; off < 1024; off <<= 1) {
        int val = src[t];
        if (t >= off) val += src[t - off];
        dst[t] = val;
        __syncthreads();
        int* tmp = src; src = dst; dst = tmp;
    }
    int incl = src[t];
    int excl = incl - s;
    if (mode == 0) {
        if (base     < NNODES) g_rank[base]     = excl;
        if (base + 1 < NNODES) g_rank[base + 1] = excl + v0;
        if (base + 2 < NNODES) g_rank[base + 2] = excl + v0 + v1;
    } else {
        if (base < NNODES) {
            g_csrptr[base] = excl; g_cursor[base] = excl;
            g_dinv[base] = rsqrtf(g_deg[base]);
        }
        if (base + 1 < NNODES) {
            g_csrptr[base + 1] = excl + v0; g_cursor[base + 1] = excl + v0;
            g_dinv[base + 1] = rsqrtf(g_deg[base + 1]);
        }
        if (base + 2 < NNODES) {
            g_csrptr[base + 2] = excl + v0 + v1; g_cursor[base + 2] = excl + v0 + v1;
            g_dinv[base + 2] = rsqrtf(g_deg[base + 2]);
        }
        if (t == 1023) g_csrptr[NNODES] = incl;
    }
}

// ---------------- remap edges + degree/counts ----------------
__global__ void k_edges(const void* eidx, const float* __restrict__ ew) {
    int e = blockIdx.x * 256 + threadIdx.x;
    if (e >= NEDGES) return;
    int is64 = g_is64;
    int sid = load_eid(eidx, e, is64);
    int did = load_eid(eidx, NEDGES + e, is64);
    int s = g_rank[sid], d = g_rank[did];
    g_esrc[e] = s;
    g_edst[e] = d;
    atomicAdd(&g_deg[d], ew[e]);
    atomicAdd(&g_counts[d], 1);
}

// ---------------- fill CSR (by dst) with normalized weights ----------------
__global__ void k_fill(const float* __restrict__ ew) {
    int e = blockIdx.x * 256 + threadIdx.x;
    if (e >= NEDGES) return;
    int d = g_edst[e], s = g_esrc[e];
    int pos = atomicAdd(&g_cursor[d], 1);
    g_csrc[pos] = s;
    g_cw[pos] = g_dinv[s] * ew[e] * g_dinv[d];
}

// ---------------- GEMM: u = x @ M via mma.sync tf32 m16n8k8, fp16 out -----------
__global__ void __launch_bounds__(128) k_gemm(const float* __restrict__ x) {
    __shared__ __align__(16) float4 Bs[16 * 4 * 32];
    int tid = threadIdx.x, wid = tid >> 5, lane = tid & 31;
    {
        const float4* s = (const float4*)g_Bfrag;
        #pragma unroll
        for (int i = 0; i < 16; i++) Bs[tid + 128 * i] = s[tid + 128 * i];
    }
    size_t rowbase = (size_t)blockIdx.x * 128;
    int grp = lane >> 2, qid = lane & 3;
    const float* px = x + (rowbase + wid * 32 + grp) * NFEAT + 4 * qid;
    __syncthreads();

    float d[14][4];
    #pragma unroll
    for (int i = 0; i < 14; i++)
        #pragma unroll
        for (int j = 0; j < 4; j++) d[i][j] = 0.f;

    #pragma unroll
    for (int t = 0; t < 8; t++) {
        float4 v0 = *(const float4*)(px + 16 * t);
        float4 v1 = *(const float4*)(px + 8 * NFEAT + 16 * t);
        float4 v2 = *(const float4*)(px + 16 * NFEAT + 16 * t);
        float4 v3 = *(const float4*)(px + 24 * NFEAT + 16 * t);
        #pragma unroll
        for (int ss = 0; ss < 2; ss++) {
            int s = 2 * t + ss;
            uint32_t am0[4], am1[4];
            if (ss == 0) {
                am0[0] = to_tf32(v0.x); am0[1] = to_tf32(v1.x);
                am0[2] = to_tf32(v0.y); am0[3] = to_tf32(v1.y);
                am1[0] = to_tf32(v2.x); am1[1] = to_tf32(v3.x);
                am1[2] = to_tf32(v2.y); am1[3] = to_tf32(v3.y);
            } else {
                am0[0] = to_tf32(v0.z); am0[1] = to_tf32(v1.z);
                am0[2] = to_tf32(v0.w); am0[3] = to_tf32(v1.w);
                am1[0] = to_tf32(v2.z); am1[1] = to_tf32(v3.z);
                am1[2] = to_tf32(v2.w); am1[3] = to_tf32(v3.w);
            }
            float4 bv[4];
            #pragma unroll
            for (int jp = 0; jp < 4; jp++) bv[jp] = Bs[(s * 4 + jp) * 32 + lane];
            const uint32_t* bu = (const uint32_t*)bv;
            #pragma unroll
            for (int jt = 0; jt < 7; jt++) {
                uint32_t b0 = bu[jt * 2], b1 = bu[jt * 2 + 1];
                mma_tf32(d[jt], am0, b0, b1);
                mma_tf32(d[7 + jt], am1, b0, b1);
            }
        }
    }
    __half2 z2 = __float2half2_rn(0.f);
    #pragma unroll
    for (int mt = 0; mt < 2; mt++) {
        size_t r0 = rowbase + wid * 32 + mt * 16 + grp;
        __half* p0 = g_u + r0 * USTR;
        #pragma unroll
        for (int jt = 0; jt < 7; jt++) {
            int c0 = jt * 8 + 2 * qid;
            __half2 lo, hi;
            if (jt < 6 || qid == 0) {
                lo = __floats2half2_rn(d[mt * 7 + jt][0], d[mt * 7 + jt][1]);
                hi = __floats2half2_rn(d[mt * 7 + jt][2], d[mt * 7 + jt][3]);
            } else { lo = z2; hi = z2; }
            *(__half2*)(p0 + c0) = lo;
            *(__half2*)(p0 + 8 * USTR + c0) = hi;
        }
        int c0 = 56 + 2 * qid;
        *(__half2*)(p0 + c0) = z2;
        *(__half2*)(p0 + 8 * USTR + c0) = z2;
    }
}

// ---------------- SpMM: warp per (n,b), n-major; 4-edge unroll per half-warp ----
__global__ void __launch_bounds__(256) k_spmm() {
    int gw = blockIdx.x * 8 + (threadIdx.x >> 5);
    int lane = threadIdx.x & 31;
    int n = gw >> 7;          // 128 batches per node, same n across CTA
    int b = gw & 127;
    const __half* ub = g_u + (size_t)b * (NNODES * USTR);
    int e0 = g_csrptr[n], e1 = g_csrptr[n + 1];
    int grp = lane >> 4, li = lane & 15;
    float ax = 0.f, ay = 0.f, az = 0.f, aw = 0.f;
    int e = e0 + grp;
    for (; e + 6 < e1; e += 8) {
        int s0 = g_csrc[e];     float w0 = g_cw[e];
        int s1 = g_csrc[e + 2]; float w1 = g_cw[e + 2];
        int s2 = g_csrc[e + 4]; float w2 = g_cw[e + 4];
        int s3 = g_csrc[e + 6]; float w3 = g_cw[e + 6];
        uint2 v0 = *(const uint2*)(ub + (size_t)s0 * USTR + li * 4);
        uint2 v1 = *(const uint2*)(ub + (size_t)s1 * USTR + li * 4);
        uint2 v2 = *(const uint2*)(ub + (size_t)s2 * USTR + li * 4);
        uint2 v3 = *(const uint2*)(ub + (size_t)s3 * USTR + li * 4);
        float2 p0 = __half22float2(*(__half2*)&v0.x);
        float2 q0 = __half22float2(*(__half2*)&v0.y);
        float2 p1 = __half22float2(*(__half2*)&v1.x);
        float2 q1 = __half22float2(*(__half2*)&v1.y);
        float2 p2 = __half22float2(*(__half2*)&v2.x);
        float2 q2 = __half22float2(*(__half2*)&v2.y);
        float2 p3 = __half22float2(*(__half2*)&v3.x);
        float2 q3 = __half22float2(*(__half2*)&v3.y);
        ax += w0 * p0.x + w1 * p1.x + w2 * p2.x + w3 * p3.x;
        ay += w0 * p0.y + w1 * p1.y + w2 * p2.y + w3 * p3.y;
        az += w0 * q0.x + w1 * q1.x + w2 * q2.x + w3 * q3.x;
        aw += w0 * q0.y + w1 * q1.y + w2 * q2.y + w3 * q3.y;
    }
    for (; e < e1; e += 2) {
        int s0 = g_csrc[e]; float w0 = g_cw[e];
        uint2 v0 = *(const uint2*)(ub + (size_t)s0 * USTR + li * 4);
        float2 p0 = __half22float2(*(__half2*)&v0.x);
        float2 q0 = __half22float2(*(__half2*)&v0.y);
        ax += w0 * p0.x; ay += w0 * p0.y;
        az += w0 * q0.x; aw += w0 * q0.y;
    }
    ax += __shfl_xor_sync(0xffffffffu, ax, 16);
    ay += __shfl_xor_sync(0xffffffffu, ay, 16);
    az += __shfl_xor_sync(0xffffffffu, az, 16);
    aw += __shfl_xor_sync(0xffffffffu, aw, 16);
    if (grp == 0 && li < 13) {
        float dv = g_dinv[n];
        float ws = dv * dv;
        uint2 vs = *(const uint2*)(ub + (size_t)n * USTR + li * 4);
        float2 ps = __half22float2(*(__half2*)&vs.x);
        float2 qs = __half22float2(*(__half2*)&vs.y);
        float4 cv = *(const float4*)(g_cvec + li * 4);
        *(float4*)(g_pre + ((size_t)b * NNODES + n) * HSP + li * 4) = make_float4(
            ax + ws * ps.x + cv.x, ay + ws * ps.y + cv.y,
            az + ws * qs.x + cv.z, aw + ws * qs.y + cv.w);
    }
}

// ---------------- RNN: warp per node, FFMA2 packed math, double-buffered h ------
__global__ void __launch_bounds__(256) k_rnn(const float* __restrict__ Whh,
                                             const float* __restrict__ bhh,
                                             const float* __restrict__ h0,
                                             float* __restrict__ out) {
    int w = blockIdx.x * 8 + (threadIdx.x >> 5);
    int lane = threadIdx.x & 31;
    if (w >= NNODES) return;
    __shared__ __align__(16) float hsm[8][2][56];
    float* hc = hsm[threadIdx.x >> 5][0];
    float* hn = hsm[threadIdx.x >> 5][1];
    bool hi = lane < 18;
    int c1 = hi ? 32 + lane : 0;
    // pack W_hh rows into f32x2 pairs (26 per output col; pair 25 = 0)
    unsigned long long w0p[26], w1p[26];
    #pragma unroll
    for (int k = 0; k < 25; k++) {
        w0p[k] = pk2(Whh[lane * HS + 2 * k], Whh[lane * HS + 2 * k + 1]);
        w1p[k] = pk2(Whh[c1 * HS + 2 * k], Whh[c1 * HS + 2 * k + 1]);
    }
    unsigned long long zz = pk2(0.f, 0.f);
    w0p[25] = zz; w1p[25] = zz;
    float b0 = bhh[lane];
    float b1 = bhh[c1];
    hc[lane] = h0[(size_t)w * HS + lane];
    if (hi) hc[32 + lane] = h0[(size_t)w * HS + 32 + lane];
    if (lane == 0) { hc[50] = 0.f; hc[51] = 0.f; hn[50] = 0.f; hn[51] = 0.f; }
    __syncwarp();
    const float* prew = g_pre + (size_t)w * HSP;
    float* outw = out + (size_t)w * HS;
    const size_t pstr = (size_t)NNODES * HSP;
    const size_t ostr = (size_t)NNODES * HS;
    float pa0 = prew[lane];
    float pa1 = hi ? prew[32 + lane] : 0.f;
    for (int t = 0; t < NB; t++) {
        float a0 = pa0 + b0;
        float a1 = pa1 + b1;
        if (t + 1 < NB) {
            pa0 = prew[pstr + lane];
            pa1 = hi ? prew[pstr + 32 + lane] : 0.f;
        }
        prew += pstr;
        unsigned long long acc0 = zz, acc1 = zz, acc2 = zz, acc3 = zz;
        #pragma unroll
        for (int kk = 0; kk < 13; kk++) {
            ulonglong2 hp = *(const ulonglong2*)&hc[kk * 4];
            acc0 = fma2(hp.x, w0p[2 * kk], acc0);
            acc1 = fma2(hp.y, w0p[2 * kk + 1], acc1);
            acc2 = fma2(hp.x, w1p[2 * kk], acc2);
            acc3 = fma2(hp.y, w1p[2 * kk + 1], acc3);
        }
        float2 u0 = upk2(acc0), u1 = upk2(acc1);
        float2 u2 = upk2(acc2), u3 = upk2(acc3);
        float t0 = fast_tanh(a0 + (u0.x + u0.y) + (u1.x + u1.y));
        float t1 = fast_tanh(a1 + (u2.x + u2.y) + (u3.x + u3.y));
        hn[lane] = t0;
        if (hi) hn[32 + lane] = t1;
        __syncwarp();
        float* tmp = hc; hc = hn; hn = tmp;
        outw[lane] = t0;
        if (hi) outw[32 + lane] = t1;
        outw += ostr;
    }
}

// ---------------- launch ----------------
extern "C" void kernel_launch(void* const* d_in, const int* in_sizes, int n_in,
                              void* d_out, int out_size) {
    const float* x    = (const float*)d_in[0];
    const void*  eidx = d_in[1];
    const float* ew   = (const float*)d_in[2];
    const float* W    = (const float*)d_in[3];
    const float* b    = (const float*)d_in[4];
    const float* W_ih = (const float*)d_in[5];
    const float* W_hh = (const float*)d_in[6];
    const float* b_ih = (const float*)d_in[7];
    const float* b_hh = (const float*)d_in[8];
    const float* h0   = (const float*)d_in[9];
    float* out = (float*)d_out;

    k_setup<<<(2 * NEDGES + 255) / 256, 256>>>(eidx, W, b, W_ih, b_ih);  // 0
    k_scan<<<1, 1024>>>(0);                                  // 1
    k_edges<<<(NEDGES + 255) / 256, 256>>>(eidx, ew);        // 2
    k_scan<<<1, 1024>>>(1);                                  // 3
    k_fill<<<(NEDGES + 255) / 256, 256>>>(ew);               // 4
    k_gemm<<<NNODES, 128>>>(x);                              // 5
    k_spmm<<<(NB * NNODES) / 8, 256>>>();                    // 6
    k_rnn<<<(NNODES + 7) / 8, 256>>>(W_hh, b_hh, h0, out);   // 7
}